// round 5
// baseline (speedup 1.0000x reference)
#include <cuda_runtime.h>
#include <math.h>
#include <stdint.h>

// ---------------- problem constants ----------------
#define S_LEN  2048
#define BATCH  2
#define DMODEL 768
#define NH     12
#define NKV    4
#define HDIM   64
#define FFDIM  3072
#define NLAYER 2
#define M_TOK  (BATCH * S_LEN)   // 4096 tokens

// ---------------- scratch (device globals; no allocation allowed) ----------
__device__ float g_h   [M_TOK * DMODEL];
__device__ float g_q   [M_TOK * DMODEL];
__device__ float g_k   [M_TOK * NKV * HDIM];
__device__ float g_v   [M_TOK * NKV * HDIM];
__device__ float g_att [M_TOK * DMODEL];
__device__ float g_x1  [M_TOK * DMODEL];
__device__ float g_x2  [M_TOK * DMODEL];
__device__ float g_gate[M_TOK * FFDIM];
__device__ float g_cosT[S_LEN * 32];
__device__ float g_sinT[S_LEN * 32];

// ---------------- helpers ----------------
__device__ __forceinline__ float tf32r(float x) {
    uint32_t u;
    asm("cvt.rna.tf32.f32 %0, %1;" : "=r"(u) : "f"(x));
    return __uint_as_float(u);
}
__device__ __forceinline__ float4 tf32r4(float4 v) {
    float4 r;
    r.x = tf32r(v.x); r.y = tf32r(v.y); r.z = tf32r(v.z); r.w = tf32r(v.w);
    return r;
}
__device__ __forceinline__ void mma_tf32(float (&c)[4],
                                         uint32_t a0, uint32_t a1, uint32_t a2, uint32_t a3,
                                         uint32_t b0, uint32_t b1) {
    asm volatile(
        "mma.sync.aligned.m16n8k8.row.col.f32.tf32.tf32.f32 "
        "{%0,%1,%2,%3}, {%4,%5,%6,%7}, {%8,%9}, {%0,%1,%2,%3};"
        : "+f"(c[0]), "+f"(c[1]), "+f"(c[2]), "+f"(c[3])
        : "r"(a0), "r"(a1), "r"(a2), "r"(a3), "r"(b0), "r"(b1));
}
#define FU(x) __float_as_uint(x)

// ---------------- RoPE tables ----------------
__global__ void rope_table_kernel(float* __restrict__ cosT, float* __restrict__ sinT) {
    int idx = blockIdx.x * blockDim.x + threadIdx.x;
    if (idx >= S_LEN * 32) return;
    int p = idx >> 5, i = idx & 31;
    double f  = exp(-((double)(2 * i) / 64.0) * log(10000.0));
    float ang = (float)p * (float)f;
    cosT[idx] = (float)cos((double)ang);
    sinT[idx] = (float)sin((double)ang);
}

// ---------------- RMSNorm (one block per row) ----------------
__global__ void rmsnorm_kernel(const float* __restrict__ x,
                               const float* __restrict__ w,
                               float* __restrict__ o) {
    int row = blockIdx.x;
    const float* xr = x + (size_t)row * DMODEL;
    float v[3];
    float s = 0.f;
#pragma unroll
    for (int t = 0; t < 3; t++) {
        v[t] = xr[threadIdx.x + t * 256];
        s += v[t] * v[t];
    }
#pragma unroll
    for (int off = 16; off > 0; off >>= 1) s += __shfl_xor_sync(0xffffffffu, s, off);
    __shared__ float red[8];
    if ((threadIdx.x & 31) == 0) red[threadIdx.x >> 5] = s;
    __syncthreads();
    float tot = 0.f;
#pragma unroll
    for (int i = 0; i < 8; i++) tot += red[i];
    float scale = rsqrtf(tot * (1.0f / (float)DMODEL) + 1e-6f);
    float* orow = o + (size_t)row * DMODEL;
#pragma unroll
    for (int t = 0; t < 3; t++) {
        int c = threadIdx.x + t * 256;
        orow[c] = v[t] * scale * w[c];
    }
}

// ---------------- RoPE apply (one block per token) ----------------
__global__ void rope_kernel(float* __restrict__ q, float* __restrict__ k,
                            const float* __restrict__ cosT,
                            const float* __restrict__ sinT) {
    int token = blockIdx.x;
    int pos = token & (S_LEN - 1);
    for (int t = threadIdx.x; t < (NH + NKV) * 32; t += 256) {
        int i  = t & 31;
        int hh = t >> 5;   // 0..11 = q heads, 12..15 = k heads
        float c = cosT[pos * 32 + i];
        float s = sinT[pos * 32 + i];
        float* base = (hh < NH) ? (q + (size_t)token * DMODEL + hh * HDIM)
                                : (k + (size_t)token * (NKV * HDIM) + (hh - NH) * HDIM);
        float t0 = base[2 * i], t1 = base[2 * i + 1];
        base[2 * i]     = t0 * c - t1 * s;
        base[2 * i + 1] = t0 * s + t1 * c;
    }
}

// ---------------- TF32 tensor-core GEMM, tile 128x64x16, 128 threads ------
// 4 warps in 2x2; each warp computes 64x32 via m16n8k8 tf32 mma.
// mode: 0 = plain, 1 = silu(acc), 2 = acc * aux[idx], 3 = acc + aux[idx]
// blockIdx.z selects (B0,O0) vs (B1,O1).
#define AS_STRIDE 20
#define BS_STRIDE 72
__global__ void __launch_bounds__(128, 4) gemm_tf32_kernel(
    const float* __restrict__ A,
    const float* __restrict__ B0, const float* __restrict__ B1,
    const float* __restrict__ aux,
    float* __restrict__ O0, float* __restrict__ O1,
    int N, int K, int mode) {
    const float* Bm = blockIdx.z ? B1 : B0;
    float*       O  = blockIdx.z ? O1 : O0;

    __shared__ float As[2][128][AS_STRIDE];
    __shared__ float Bs[2][16][BS_STRIDE];

    const int tid  = threadIdx.x;
    const int lane = tid & 31;
    const int warp = tid >> 5;
    const int wm   = warp & 1;    // 0..1 -> rows wm*64
    const int wn   = warp >> 1;   // 0..1 -> cols wn*32
    const int rowBase = blockIdx.y * 128;
    const int colBase = blockIdx.x * 64;

    // staging indices
    const int ar  = tid >> 1;            // 0..63 (A rows ar, ar+64)
    const int ac  = (tid & 1) * 8;       // 0 or 8
    const int bkr = tid >> 3;            // 0..15 (B k row)
    const int bnc = (tid & 7) * 8;       // 0..56 (B col chunk of 8)

    const int lq = lane >> 2;            // 0..7
    const int lr = lane & 3;             // 0..3

    float acc[4][4][4];
#pragma unroll
    for (int i = 0; i < 4; i++)
#pragma unroll
        for (int j = 0; j < 4; j++)
#pragma unroll
            for (int t = 0; t < 4; t++) acc[i][j][t] = 0.f;

    float4 pa0, pa1, pa2, pa3, pb0, pb1;
    const int T = K / 16;

    // preload tile 0
    {
        const float* Ap = A + (size_t)(rowBase + ar) * K + ac;
        pa0 = *(const float4*)(Ap);
        pa1 = *(const float4*)(Ap + 4);
        const float* Ap2 = Ap + (size_t)64 * K;
        pa2 = *(const float4*)(Ap2);
        pa3 = *(const float4*)(Ap2 + 4);
        const float* Bp = Bm + (size_t)bkr * N + colBase + bnc;
        pb0 = *(const float4*)(Bp);
        pb1 = *(const float4*)(Bp + 4);
    }
    *(float4*)&As[0][ar][ac]           = tf32r4(pa0);
    *(float4*)&As[0][ar][ac + 4]       = tf32r4(pa1);
    *(float4*)&As[0][ar + 64][ac]      = tf32r4(pa2);
    *(float4*)&As[0][ar + 64][ac + 4]  = tf32r4(pa3);
    *(float4*)&Bs[0][bkr][bnc]         = tf32r4(pb0);
    *(float4*)&Bs[0][bkr][bnc + 4]     = tf32r4(pb1);
    __syncthreads();

    for (int t = 0; t < T; t++) {
        if (t + 1 < T) {
            const float* Ap = A + (size_t)(rowBase + ar) * K + (t + 1) * 16 + ac;
            pa0 = *(const float4*)(Ap);
            pa1 = *(const float4*)(Ap + 4);
            const float* Ap2 = Ap + (size_t)64 * K;
            pa2 = *(const float4*)(Ap2);
            pa3 = *(const float4*)(Ap2 + 4);
            const float* Bp = Bm + (size_t)((t + 1) * 16 + bkr) * N + colBase + bnc;
            pb0 = *(const float4*)(Bp);
            pb1 = *(const float4*)(Bp + 4);
        }
        const int buf = t & 1;
#pragma unroll
        for (int kf = 0; kf < 2; kf++) {
            const int k0 = kf * 8;
            uint32_t af[4][4];
#pragma unroll
            for (int mf = 0; mf < 4; mf++) {
                int row0 = wm * 64 + mf * 16 + lq;
                af[mf][0] = FU(As[buf][row0    ][k0 + lr]);
                af[mf][1] = FU(As[buf][row0 + 8][k0 + lr]);
                af[mf][2] = FU(As[buf][row0    ][k0 + lr + 4]);
                af[mf][3] = FU(As[buf][row0 + 8][k0 + lr + 4]);
            }
#pragma unroll
            for (int nf = 0; nf < 4; nf++) {
                int col0 = wn * 32 + nf * 8 + lq;
                uint32_t b0 = FU(Bs[buf][k0 + lr    ][col0]);
                uint32_t b1 = FU(Bs[buf][k0 + lr + 4][col0]);
#pragma unroll
                for (int mf = 0; mf < 4; mf++)
                    mma_tf32(acc[mf][nf], af[mf][0], af[mf][1], af[mf][2], af[mf][3], b0, b1);
            }
        }
        if (t + 1 < T) {
            const int nbuf = buf ^ 1;
            *(float4*)&As[nbuf][ar][ac]          = tf32r4(pa0);
            *(float4*)&As[nbuf][ar][ac + 4]      = tf32r4(pa1);
            *(float4*)&As[nbuf][ar + 64][ac]     = tf32r4(pa2);
            *(float4*)&As[nbuf][ar + 64][ac + 4] = tf32r4(pa3);
            *(float4*)&Bs[nbuf][bkr][bnc]        = tf32r4(pb0);
            *(float4*)&Bs[nbuf][bkr][bnc + 4]    = tf32r4(pb1);
        }
        __syncthreads();
    }

    // epilogue
#pragma unroll
    for (int mf = 0; mf < 4; mf++) {
        int row0 = rowBase + wm * 64 + mf * 16 + lq;
#pragma unroll
        for (int nf = 0; nf < 4; nf++) {
            int col = colBase + wn * 32 + nf * 8 + 2 * lr;
#pragma unroll
            for (int half = 0; half < 2; half++) {
                int row = row0 + half * 8;
                size_t idx = (size_t)row * N + col;
                float v0 = acc[mf][nf][half * 2];
                float v1 = acc[mf][nf][half * 2 + 1];
                if (mode == 1) {
                    v0 = v0 / (1.f + __expf(-v0));
                    v1 = v1 / (1.f + __expf(-v1));
                } else if (mode == 2) {
                    v0 *= aux[idx]; v1 *= aux[idx + 1];
                } else if (mode == 3) {
                    v0 += aux[idx]; v1 += aux[idx + 1];
                }
                float2 o2 = make_float2(v0, v1);
                *(float2*)(O + idx) = o2;
            }
        }
    }
}

// ---------------- Flash attention, TF32 mma (causal, GQA) ----------------
#define AT_PAD 72
#define FLASH_SMEM (4 * 64 * AT_PAD * 4)   // Qs, Ks, Vs, Ps

__global__ void __launch_bounds__(128) flash_tf32_kernel(
    const float* __restrict__ q, const float* __restrict__ k,
    const float* __restrict__ v, float* __restrict__ o) {
    extern __shared__ float sm[];
    float* Qs = sm;
    float* Ks = sm + 64 * AT_PAD;
    float* Vs = sm + 2 * 64 * AT_PAD;
    float* Ps = sm + 3 * 64 * AT_PAD;

    const int qb  = (gridDim.x - 1) - blockIdx.x;   // heavy blocks first
    const int bh  = blockIdx.y;
    const int b   = bh / NH;
    const int h   = bh % NH;
    const int kvh = h / (NH / NKV);
    const int tid  = threadIdx.x;
    const int lane = tid & 31;
    const int warp = tid >> 5;
    const int lq = lane >> 2;     // 0..7
    const int lr = lane & 3;      // 0..3

    // load Q tile [64 x 64] (cvt to tf32)
    for (int t = tid; t < 64 * 16; t += 128) {
        int r = t >> 4, c4 = (t & 15) << 2;
        float4 vv = *(const float4*)(q + ((size_t)((b * S_LEN + qb * 64 + r) * NH + h)) * HDIM + c4);
        vv = tf32r4(vv);
        float* dst = Qs + r * AT_PAD + c4;
        dst[0] = vv.x; dst[1] = vv.y; dst[2] = vv.z; dst[3] = vv.w;
    }

    const int r0l = warp * 16 + lq;     // local q row (and +8)
    const int qrow0 = qb * 64 + r0l;
    const int qrow1 = qrow0 + 8;

    float m0 = -1e30f, m1 = -1e30f, l0 = 0.f, l1 = 0.f;
    float oacc[8][4];
#pragma unroll
    for (int nf = 0; nf < 8; nf++)
#pragma unroll
        for (int t = 0; t < 4; t++) oacc[nf][t] = 0.f;

    for (int kb = 0; kb <= qb; kb++) {
        __syncthreads();   // all warps done with previous Ks/Vs
        for (int t = tid; t < 64 * 16; t += 128) {
            int r = t >> 4, c4 = (t & 15) << 2;
            size_t goff = ((size_t)((b * S_LEN + kb * 64 + r) * NKV + kvh)) * HDIM + c4;
            float4 k4 = tf32r4(*(const float4*)(k + goff));
            float* kd = Ks + r * AT_PAD + c4;
            kd[0] = k4.x; kd[1] = k4.y; kd[2] = k4.z; kd[3] = k4.w;
            float4 v4 = tf32r4(*(const float4*)(v + goff));
            float* vd = Vs + r * AT_PAD + c4;
            vd[0] = v4.x; vd[1] = v4.y; vd[2] = v4.z; vd[3] = v4.w;
        }
        __syncthreads();

        // ---- S = Q K^T (16 x 64 per warp) ----
        float sacc[8][4];
#pragma unroll
        for (int nf = 0; nf < 8; nf++)
#pragma unroll
            for (int t = 0; t < 4; t++) sacc[nf][t] = 0.f;

#pragma unroll
        for (int kf = 0; kf < 8; kf++) {
            const int kk = kf * 8 + lr;
            uint32_t a0 = FU(Qs[r0l * AT_PAD + kk]);
            uint32_t a1 = FU(Qs[(r0l + 8) * AT_PAD + kk]);
            uint32_t a2 = FU(Qs[r0l * AT_PAD + kk + 4]);
            uint32_t a3 = FU(Qs[(r0l + 8) * AT_PAD + kk + 4]);
#pragma unroll
            for (int nf = 0; nf < 8; nf++) {
                int j = nf * 8 + lq;
                uint32_t b0 = FU(Ks[j * AT_PAD + kk]);
                uint32_t b1 = FU(Ks[j * AT_PAD + kk + 4]);
                mma_tf32(sacc[nf], a0, a1, a2, a3, b0, b1);
            }
        }

        // ---- scale, mask, online softmax ----
        const bool diag = (kb == qb);
        float rmax0 = -1e30f, rmax1 = -1e30f;
#pragma unroll
        for (int nf = 0; nf < 8; nf++) {
            int jc = kb * 64 + nf * 8 + 2 * lr;
            float s0 = sacc[nf][0] * 0.125f;
            float s1 = sacc[nf][1] * 0.125f;
            float s2 = sacc[nf][2] * 0.125f;
            float s3 = sacc[nf][3] * 0.125f;
            if (diag) {
                if (jc     > qrow0) s0 = -1e30f;
                if (jc + 1 > qrow0) s1 = -1e30f;
                if (jc     > qrow1) s2 = -1e30f;
                if (jc + 1 > qrow1) s3 = -1e30f;
            }
            sacc[nf][0] = s0; sacc[nf][1] = s1; sacc[nf][2] = s2; sacc[nf][3] = s3;
            rmax0 = fmaxf(rmax0, fmaxf(s0, s1));
            rmax1 = fmaxf(rmax1, fmaxf(s2, s3));
        }
        rmax0 = fmaxf(rmax0, __shfl_xor_sync(0xffffffffu, rmax0, 1));
        rmax0 = fmaxf(rmax0, __shfl_xor_sync(0xffffffffu, rmax0, 2));
        rmax1 = fmaxf(rmax1, __shfl_xor_sync(0xffffffffu, rmax1, 1));
        rmax1 = fmaxf(rmax1, __shfl_xor_sync(0xffffffffu, rmax1, 2));

        float mn0 = fmaxf(m0, rmax0);
        float mn1 = fmaxf(m1, rmax1);
        float alpha0 = __expf(m0 - mn0);
        float alpha1 = __expf(m1 - mn1);
        m0 = mn0; m1 = mn1;

        float rsum0 = 0.f, rsum1 = 0.f;
#pragma unroll
        for (int nf = 0; nf < 8; nf++) {
            float p0 = __expf(sacc[nf][0] - mn0);
            float p1 = __expf(sacc[nf][1] - mn0);
            float p2 = __expf(sacc[nf][2] - mn1);
            float p3 = __expf(sacc[nf][3] - mn1);
            sacc[nf][0] = p0; sacc[nf][1] = p1; sacc[nf][2] = p2; sacc[nf][3] = p3;
            rsum0 += p0 + p1;
            rsum1 += p2 + p3;
        }
        rsum0 += __shfl_xor_sync(0xffffffffu, rsum0, 1);
        rsum0 += __shfl_xor_sync(0xffffffffu, rsum0, 2);
        rsum1 += __shfl_xor_sync(0xffffffffu, rsum1, 1);
        rsum1 += __shfl_xor_sync(0xffffffffu, rsum1, 2);
        l0 = l0 * alpha0 + rsum0;
        l1 = l1 * alpha1 + rsum1;

#pragma unroll
        for (int nf = 0; nf < 8; nf++) {
            oacc[nf][0] *= alpha0; oacc[nf][1] *= alpha0;
            oacc[nf][2] *= alpha1; oacc[nf][3] *= alpha1;
        }

        // ---- stage P (tf32) to smem for PV mma ----
#pragma unroll
        for (int nf = 0; nf < 8; nf++) {
            int pc = nf * 8 + 2 * lr;
            float* p0 = Ps + r0l * AT_PAD + pc;
            p0[0] = tf32r(sacc[nf][0]); p0[1] = tf32r(sacc[nf][1]);
            float* p1 = Ps + (r0l + 8) * AT_PAD + pc;
            p1[0] = tf32r(sacc[nf][2]); p1[1] = tf32r(sacc[nf][3]);
        }
        __syncwarp();

        // ---- O += P V ----
#pragma unroll
        for (int kf = 0; kf < 8; kf++) {
            const int kk = kf * 8 + lr;
            uint32_t a0 = FU(Ps[r0l * AT_PAD + kk]);
            uint32_t a1 = FU(Ps[(r0l + 8) * AT_PAD + kk]);
            uint32_t a2 = FU(Ps[r0l * AT_PAD + kk + 4]);
            uint32_t a3 = FU(Ps[(r0l + 8) * AT_PAD + kk + 4]);
#pragma unroll
            for (int nf = 0; nf < 8; nf++) {
                int d = nf * 8 + lq;
                uint32_t b0 = FU(Vs[(kf * 8 + lr) * AT_PAD + d]);
                uint32_t b1 = FU(Vs[(kf * 8 + lr + 4) * AT_PAD + d]);
                mma_tf32(oacc[nf], a0, a1, a2, a3, b0, b1);
            }
        }
    }

    // ---- epilogue ----
    float inv0 = 1.f / l0;
    float inv1 = 1.f / l1;
    int grow0 = b * S_LEN + qrow0;
    int grow1 = b * S_LEN + qrow1;
#pragma unroll
    for (int nf = 0; nf < 8; nf++) {
        int col = nf * 8 + 2 * lr;
        float2 v0 = make_float2(oacc[nf][0] * inv0, oacc[nf][1] * inv0);
        float2 v1 = make_float2(oacc[nf][2] * inv1, oacc[nf][3] * inv1);
        *(float2*)(o + ((size_t)(grow0 * NH + h)) * HDIM + col) = v0;
        *(float2*)(o + ((size_t)(grow1 * NH + h)) * HDIM + col) = v1;
    }
}

// ---------------- launch ----------------
extern "C" void kernel_launch(void* const* d_in, const int* in_sizes, int n_in,
                              void* d_out, int out_size) {
    const float* x  = (const float*)d_in[0];
    const float* Wq = (const float*)d_in[1];
    const float* Wk = (const float*)d_in[2];
    const float* Wv = (const float*)d_in[3];
    const float* Wo = (const float*)d_in[4];
    const float* an = (const float*)d_in[5];
    const float* w0 = (const float*)d_in[6];
    const float* w1 = (const float*)d_in[7];
    const float* w2 = (const float*)d_in[8];
    const float* sn = (const float*)d_in[9];
    const float* on = (const float*)d_in[10];
    float* out = (float*)d_out;

    float *h, *q, *k, *v, *att, *x1, *x2, *gate, *cosT, *sinT;
    cudaGetSymbolAddress((void**)&h,    g_h);
    cudaGetSymbolAddress((void**)&q,    g_q);
    cudaGetSymbolAddress((void**)&k,    g_k);
    cudaGetSymbolAddress((void**)&v,    g_v);
    cudaGetSymbolAddress((void**)&att,  g_att);
    cudaGetSymbolAddress((void**)&x1,   g_x1);
    cudaGetSymbolAddress((void**)&x2,   g_x2);
    cudaGetSymbolAddress((void**)&gate, g_gate);
    cudaGetSymbolAddress((void**)&cosT, g_cosT);
    cudaGetSymbolAddress((void**)&sinT, g_sinT);

    cudaFuncSetAttribute(flash_tf32_kernel,
                         cudaFuncAttributeMaxDynamicSharedMemorySize, FLASH_SMEM);

    rope_table_kernel<<<(S_LEN * 32 + 255) / 256, 256>>>(cosT, sinT);

    const dim3 gN768 (DMODEL / 64, M_TOK / 128, 1);
    const dim3 gKV   ((NKV * HDIM) / 64, M_TOK / 128, 2);
    const dim3 gFF   (FFDIM / 64, M_TOK / 128, 1);

    const float* xin = x;
    for (int l = 0; l < NLAYER; l++) {
        const float* Wq_l = Wq + (size_t)l * DMODEL * DMODEL;
        const float* Wk_l = Wk + (size_t)l * DMODEL * (NKV * HDIM);
        const float* Wv_l = Wv + (size_t)l * DMODEL * (NKV * HDIM);
        const float* Wo_l = Wo + (size_t)l * DMODEL * DMODEL;
        const float* w0_l = w0 + (size_t)l * DMODEL * FFDIM;
        const float* w1_l = w1 + (size_t)l * DMODEL * FFDIM;
        const float* w2_l = w2 + (size_t)l * FFDIM * DMODEL;

        rmsnorm_kernel<<<M_TOK, 256>>>(xin, an + l * DMODEL, h);
        gemm_tf32_kernel<<<gN768, 128>>>(h, Wq_l, Wq_l, nullptr, q, q, DMODEL, DMODEL, 0);
        gemm_tf32_kernel<<<gKV,   128>>>(h, Wk_l, Wv_l, nullptr, k, v, NKV * HDIM, DMODEL, 0);
        rope_kernel<<<M_TOK, 256>>>(q, k, cosT, sinT);
        flash_tf32_kernel<<<dim3(S_LEN / 64, BATCH * NH), 128, FLASH_SMEM>>>(q, k, v, att);
        gemm_tf32_kernel<<<gN768, 128>>>(att, Wo_l, Wo_l, xin, x1, x1, DMODEL, DMODEL, 3);
        rmsnorm_kernel<<<M_TOK, 256>>>(x1, sn + l * DMODEL, h);
        gemm_tf32_kernel<<<gFF, 128>>>(h, w0_l, w0_l, nullptr, gate, gate, FFDIM, DMODEL, 1);
        gemm_tf32_kernel<<<gFF, 128>>>(h, w1_l, w1_l, gate, gate, gate, FFDIM, DMODEL, 2);
        gemm_tf32_kernel<<<gN768, 128>>>(gate, w2_l, w2_l, x1, x2, x2, DMODEL, FFDIM, 3);
        xin = x2;
    }
    rmsnorm_kernel<<<M_TOK, 256>>>(x2, on, out);
}

// round 6
// speedup vs baseline: 1.8319x; 1.8319x over previous
#include <cuda_runtime.h>
#include <cuda_fp16.h>
#include <math.h>
#include <stdint.h>

// ---------------- problem constants ----------------
#define S_LEN  2048
#define BATCH  2
#define DMODEL 768
#define NH     12
#define NKV    4
#define HDIM   64
#define FFDIM  3072
#define NLAYER 2
#define M_TOK  (BATCH * S_LEN)   // 4096 tokens
#define KVD    (NKV * HDIM)      // 256

// ---------------- scratch (device globals; no allocation allowed) ----------
__device__ __align__(16) __half g_h   [M_TOK * DMODEL];
__device__ __align__(16) __half g_q   [M_TOK * DMODEL];
__device__ __align__(16) __half g_k   [M_TOK * KVD];
__device__ __align__(16) __half g_v   [M_TOK * KVD];
__device__ __align__(16) __half g_att [M_TOK * DMODEL];
__device__ __align__(16) __half g_gate[M_TOK * FFDIM];
__device__ __align__(16) float  g_x1  [M_TOK * DMODEL];
__device__ __align__(16) float  g_x2  [M_TOK * DMODEL];
__device__ __align__(16) float  g_cosT[S_LEN * 32];
__device__ __align__(16) float  g_sinT[S_LEN * 32];
// fp16 transposed weights [N][K] per layer
__device__ __align__(16) __half g_hWq[NLAYER * DMODEL * DMODEL];
__device__ __align__(16) __half g_hWk[NLAYER * KVD * DMODEL];
__device__ __align__(16) __half g_hWv[NLAYER * KVD * DMODEL];
__device__ __align__(16) __half g_hWo[NLAYER * DMODEL * DMODEL];
__device__ __align__(16) __half g_hw0[NLAYER * FFDIM * DMODEL];
__device__ __align__(16) __half g_hw1[NLAYER * FFDIM * DMODEL];
__device__ __align__(16) __half g_hw2[NLAYER * DMODEL * FFDIM];

// ---------------- helpers ----------------
__device__ __forceinline__ void mma_f16(float (&c)[4],
                                        uint32_t a0, uint32_t a1, uint32_t a2, uint32_t a3,
                                        uint32_t b0, uint32_t b1) {
    asm volatile(
        "mma.sync.aligned.m16n8k16.row.col.f32.f16.f16.f32 "
        "{%0,%1,%2,%3}, {%4,%5,%6,%7}, {%8,%9}, {%0,%1,%2,%3};"
        : "+f"(c[0]), "+f"(c[1]), "+f"(c[2]), "+f"(c[3])
        : "r"(a0), "r"(a1), "r"(a2), "r"(a3), "r"(b0), "r"(b1));
}
__device__ __forceinline__ void mma_tf32(float (&c)[4],
                                         uint32_t a0, uint32_t a1, uint32_t a2, uint32_t a3,
                                         uint32_t b0, uint32_t b1) {
    asm volatile(
        "mma.sync.aligned.m16n8k8.row.col.f32.tf32.tf32.f32 "
        "{%0,%1,%2,%3}, {%4,%5,%6,%7}, {%8,%9}, {%0,%1,%2,%3};"
        : "+f"(c[0]), "+f"(c[1]), "+f"(c[2]), "+f"(c[3])
        : "r"(a0), "r"(a1), "r"(a2), "r"(a3), "r"(b0), "r"(b1));
}
#define FU(x) __float_as_uint(x)
__device__ __forceinline__ void cpa16(uint32_t d, const void* s) {
    asm volatile("cp.async.cg.shared.global [%0], [%1], 16;" :: "r"(d), "l"(s));
}
__device__ __forceinline__ void cpcommit() { asm volatile("cp.async.commit_group;"); }
__device__ __forceinline__ void cpwait1()  { asm volatile("cp.async.wait_group 1;"); }

// ---------------- RoPE tables ----------------
__global__ void rope_table_kernel(float* __restrict__ cosT, float* __restrict__ sinT) {
    int idx = blockIdx.x * blockDim.x + threadIdx.x;
    if (idx >= S_LEN * 32) return;
    int p = idx >> 5, i = idx & 31;
    double f  = exp(-((double)(2 * i) / 64.0) * log(10000.0));
    float ang = (float)p * (float)f;
    cosT[idx] = (float)cos((double)ang);
    sinT[idx] = (float)sin((double)ang);
}

// ---------------- weight transpose + fp16 convert: src[K][N] -> dst[N][K] --
__global__ void w_t_h_kernel(const float* __restrict__ src, __half* __restrict__ dst,
                             int K, int N) {
    __shared__ float tile[32][33];
    int l = blockIdx.z;
    src += (size_t)l * K * N;
    dst += (size_t)l * K * N;
    int nb = blockIdx.x * 32, kb = blockIdx.y * 32;
    int tx = threadIdx.x, ty = threadIdx.y;   // 32 x 8
#pragma unroll
    for (int i = 0; i < 4; i++)
        tile[ty + 8 * i][tx] = src[(size_t)(kb + ty + 8 * i) * N + nb + tx];
    __syncthreads();
#pragma unroll
    for (int i = 0; i < 4; i++)
        dst[(size_t)(nb + ty + 8 * i) * K + kb + tx] = __float2half_rn(tile[tx][ty + 8 * i]);
}

// ---------------- RMSNorm (fp32 in -> fp16 out, or fp32 out if oh==null) ---
__global__ void rmsnorm_kernel(const float* __restrict__ x,
                               const float* __restrict__ w,
                               __half* __restrict__ oh,
                               float* __restrict__ of) {
    int row = blockIdx.x;
    const float* xr = x + (size_t)row * DMODEL;
    float v[3];
    float s = 0.f;
#pragma unroll
    for (int t = 0; t < 3; t++) {
        v[t] = xr[threadIdx.x + t * 256];
        s += v[t] * v[t];
    }
#pragma unroll
    for (int off = 16; off > 0; off >>= 1) s += __shfl_xor_sync(0xffffffffu, s, off);
    __shared__ float red[8];
    if ((threadIdx.x & 31) == 0) red[threadIdx.x >> 5] = s;
    __syncthreads();
    float tot = 0.f;
#pragma unroll
    for (int i = 0; i < 8; i++) tot += red[i];
    float scale = rsqrtf(tot * (1.0f / (float)DMODEL) + 1e-6f);
    if (oh) {
        __half* orow = oh + (size_t)row * DMODEL;
#pragma unroll
        for (int t = 0; t < 3; t++) {
            int c = threadIdx.x + t * 256;
            orow[c] = __float2half_rn(v[t] * scale * w[c]);
        }
    } else {
        float* orow = of + (size_t)row * DMODEL;
#pragma unroll
        for (int t = 0; t < 3; t++) {
            int c = threadIdx.x + t * 256;
            orow[c] = v[t] * scale * w[c];
        }
    }
}

// ---------------- RoPE apply on fp16 q/k (one block per token) -------------
__global__ void rope_kernel(__half* __restrict__ q, __half* __restrict__ k,
                            const float* __restrict__ cosT,
                            const float* __restrict__ sinT) {
    int token = blockIdx.x;
    int pos = token & (S_LEN - 1);
    for (int t = threadIdx.x; t < (NH + NKV) * 32; t += 256) {
        int i  = t & 31;
        int hh = t >> 5;   // 0..11 = q heads, 12..15 = k heads
        float c = cosT[pos * 32 + i];
        float s = sinT[pos * 32 + i];
        __half2* base = (hh < NH)
            ? (__half2*)(q + (size_t)token * DMODEL + hh * HDIM)
            : (__half2*)(k + (size_t)token * KVD + (hh - NH) * HDIM);
        __half2 p = base[i];
        float t0 = __low2float(p), t1 = __high2float(p);
        base[i] = __floats2half2_rn(t0 * c - t1 * s, t0 * s + t1 * c);
    }
}

// ---------------- FP16 tensor-core GEMM, tile 128x128x32, cp.async 3-stage -
// A [M][K] fp16 row-major; Bt [N][K] fp16 (transposed weights).
// mode: 0 plain(h16 out), 1 silu(h16 out), 2 acc*aux16(h16 out), 3 acc+aux32(f32 out)
// blockIdx.z selects (B0t,O0) vs (B1t,O1).
#define KT   32
#define STG  3
#define AST  40   // halfs per A smem row (32 + 8 pad)
#define BST  40
#define GEMM_SMEM ((STG * 128 * AST + STG * 128 * BST) * 2)   // 61440 bytes

__global__ void __launch_bounds__(256, 2) gemm_f16_kernel(
    const __half* __restrict__ A,
    const __half* __restrict__ B0t, const __half* __restrict__ B1t,
    const void* __restrict__ aux,
    void* __restrict__ O0, void* __restrict__ O1,
    int N, int K, int mode) {
    const __half* Bt = blockIdx.z ? B1t : B0t;
    void*         O  = blockIdx.z ? O1 : O0;
    extern __shared__ __half sm[];
    __half* Asm = sm;                        // [STG][128][AST]
    __half* Bsm = sm + STG * 128 * AST;      // [STG][128][BST]
    uint32_t aBase = (uint32_t)__cvta_generic_to_shared(Asm);
    uint32_t bBase = (uint32_t)__cvta_generic_to_shared(Bsm);

    const int tid  = threadIdx.x;
    const int lane = tid & 31;
    const int warp = tid >> 5;
    const int wm   = warp & 1;     // rows wm*64
    const int wn   = warp >> 1;    // cols wn*32
    const int rowBase = blockIdx.y * 128;
    const int colBase = blockIdx.x * 128;
    const int lq = lane >> 2;
    const int lr = lane & 3;

    float acc[4][4][4];
#pragma unroll
    for (int i = 0; i < 4; i++)
#pragma unroll
        for (int j = 0; j < 4; j++)
#pragma unroll
            for (int t = 0; t < 4; t++) acc[i][j][t] = 0.f;

    const int T = K / KT;

    auto stage = [&](int s, int kt) {
#pragma unroll
        for (int c0 = 0; c0 < 2; c0++) {
            int c = tid + c0 * 256;
            int r = c >> 2, k8 = (c & 3) * 8;
            cpa16(aBase + (uint32_t)(s * 128 * AST + r * AST + k8) * 2,
                  A  + (size_t)(rowBase + r) * K + kt * KT + k8);
            cpa16(bBase + (uint32_t)(s * 128 * BST + r * BST + k8) * 2,
                  Bt + (size_t)(colBase + r) * K + kt * KT + k8);
        }
    };

    stage(0, 0); cpcommit();
    stage(1, 1); cpcommit();

    for (int t = 0; t < T; t++) {
        cpwait1();
        __syncthreads();
        if (t + 2 < T) stage((t + 2) % STG, t + 2);
        cpcommit();

        const __half* Ab = Asm + (t % STG) * 128 * AST;
        const __half* Bb = Bsm + (t % STG) * 128 * BST;
#pragma unroll
        for (int kf = 0; kf < 2; kf++) {
            const int k0 = kf * 16;
            uint32_t af[4][4];
#pragma unroll
            for (int mf = 0; mf < 4; mf++) {
                int r0 = wm * 64 + mf * 16 + lq;
                af[mf][0] = *(const uint32_t*)(Ab + r0 * AST + k0 + 2 * lr);
                af[mf][1] = *(const uint32_t*)(Ab + (r0 + 8) * AST + k0 + 2 * lr);
                af[mf][2] = *(const uint32_t*)(Ab + r0 * AST + k0 + 8 + 2 * lr);
                af[mf][3] = *(const uint32_t*)(Ab + (r0 + 8) * AST + k0 + 8 + 2 * lr);
            }
#pragma unroll
            for (int nf = 0; nf < 4; nf++) {
                int c0 = wn * 32 + nf * 8 + lq;
                uint32_t b0 = *(const uint32_t*)(Bb + c0 * BST + k0 + 2 * lr);
                uint32_t b1 = *(const uint32_t*)(Bb + c0 * BST + k0 + 8 + 2 * lr);
#pragma unroll
                for (int mf = 0; mf < 4; mf++)
                    mma_f16(acc[mf][nf], af[mf][0], af[mf][1], af[mf][2], af[mf][3], b0, b1);
            }
        }
    }
    __syncthreads();

    // epilogue
#pragma unroll
    for (int mf = 0; mf < 4; mf++) {
        int row0 = rowBase + wm * 64 + mf * 16 + lq;
#pragma unroll
        for (int nf = 0; nf < 4; nf++) {
            int col = colBase + wn * 32 + nf * 8 + 2 * lr;
#pragma unroll
            for (int hh = 0; hh < 2; hh++) {
                int row = row0 + hh * 8;
                size_t idx = (size_t)row * N + col;
                float v0 = acc[mf][nf][hh * 2];
                float v1 = acc[mf][nf][hh * 2 + 1];
                if (mode == 3) {
                    float2 a2 = *(const float2*)((const float*)aux + idx);
                    *(float2*)((float*)O + idx) = make_float2(v0 + a2.x, v1 + a2.y);
                } else {
                    if (mode == 1) {
                        v0 = v0 / (1.f + __expf(-v0));
                        v1 = v1 / (1.f + __expf(-v1));
                    } else if (mode == 2) {
                        __half2 g2 = *(const __half2*)((const __half*)aux + idx);
                        v0 *= __low2float(g2);
                        v1 *= __high2float(g2);
                    }
                    *(__half2*)((__half*)O + idx) = __floats2half2_rn(v0, v1);
                }
            }
        }
    }
}

// ---------------- Flash attention, TF32 mma (causal, GQA), fp16 I/O -------
#define AT_PAD 72
#define FLASH_SMEM (4 * 64 * AT_PAD * 4)   // Qs, Ks, Vs, Ps

__global__ void __launch_bounds__(128) flash_tf32_kernel(
    const __half* __restrict__ q, const __half* __restrict__ k,
    const __half* __restrict__ v, __half* __restrict__ o) {
    extern __shared__ float smf[];
    float* Qs = smf;
    float* Ks = smf + 64 * AT_PAD;
    float* Vs = smf + 2 * 64 * AT_PAD;
    float* Ps = smf + 3 * 64 * AT_PAD;

    const int qb  = (gridDim.x - 1) - blockIdx.x;   // heavy blocks first
    const int bh  = blockIdx.y;
    const int b   = bh / NH;
    const int h   = bh % NH;
    const int kvh = h / (NH / NKV);
    const int tid  = threadIdx.x;
    const int lane = tid & 31;
    const int warp = tid >> 5;
    const int lq = lane >> 2;
    const int lr = lane & 3;

    // load Q tile [64 x 64] (half -> float)
    for (int t = tid; t < 64 * 8; t += 128) {
        int r = t >> 3, c8 = (t & 7) * 8;
        uint4 raw = *(const uint4*)(q + ((size_t)((b * S_LEN + qb * 64 + r) * NH + h)) * HDIM + c8);
        const __half2* hp = (const __half2*)&raw;
        float* dst = Qs + r * AT_PAD + c8;
#pragma unroll
        for (int j = 0; j < 4; j++) {
            float2 f = __half22float2(hp[j]);
            dst[2 * j] = f.x; dst[2 * j + 1] = f.y;
        }
    }

    const int r0l = warp * 16 + lq;
    const int qrow0 = qb * 64 + r0l;
    const int qrow1 = qrow0 + 8;

    float m0 = -1e30f, m1 = -1e30f, l0 = 0.f, l1 = 0.f;
    float oacc[8][4];
#pragma unroll
    for (int nf = 0; nf < 8; nf++)
#pragma unroll
        for (int t = 0; t < 4; t++) oacc[nf][t] = 0.f;

    for (int kb = 0; kb <= qb; kb++) {
        __syncthreads();
        for (int t = tid; t < 64 * 8; t += 128) {
            int r = t >> 3, c8 = (t & 7) * 8;
            size_t goff = ((size_t)((b * S_LEN + kb * 64 + r) * NKV + kvh)) * HDIM + c8;
            uint4 kraw = *(const uint4*)(k + goff);
            uint4 vraw = *(const uint4*)(v + goff);
            const __half2* kp = (const __half2*)&kraw;
            const __half2* vp = (const __half2*)&vraw;
            float* kd = Ks + r * AT_PAD + c8;
            float* vd = Vs + r * AT_PAD + c8;
#pragma unroll
            for (int j = 0; j < 4; j++) {
                float2 kf2 = __half22float2(kp[j]);
                kd[2 * j] = kf2.x; kd[2 * j + 1] = kf2.y;
                float2 vf2 = __half22float2(vp[j]);
                vd[2 * j] = vf2.x; vd[2 * j + 1] = vf2.y;
            }
        }
        __syncthreads();

        // ---- S = Q K^T ----
        float sacc[8][4];
#pragma unroll
        for (int nf = 0; nf < 8; nf++)
#pragma unroll
            for (int t = 0; t < 4; t++) sacc[nf][t] = 0.f;

#pragma unroll
        for (int kf = 0; kf < 8; kf++) {
            const int kk = kf * 8 + lr;
            uint32_t a0 = FU(Qs[r0l * AT_PAD + kk]);
            uint32_t a1 = FU(Qs[(r0l + 8) * AT_PAD + kk]);
            uint32_t a2 = FU(Qs[r0l * AT_PAD + kk + 4]);
            uint32_t a3 = FU(Qs[(r0l + 8) * AT_PAD + kk + 4]);
#pragma unroll
            for (int nf = 0; nf < 8; nf++) {
                int j = nf * 8 + lq;
                uint32_t b0 = FU(Ks[j * AT_PAD + kk]);
                uint32_t b1 = FU(Ks[j * AT_PAD + kk + 4]);
                mma_tf32(sacc[nf], a0, a1, a2, a3, b0, b1);
            }
        }

        // ---- scale, mask, online softmax ----
        const bool diag = (kb == qb);
        float rmax0 = -1e30f, rmax1 = -1e30f;
#pragma unroll
        for (int nf = 0; nf < 8; nf++) {
            int jc = kb * 64 + nf * 8 + 2 * lr;
            float s0 = sacc[nf][0] * 0.125f;
            float s1 = sacc[nf][1] * 0.125f;
            float s2 = sacc[nf][2] * 0.125f;
            float s3 = sacc[nf][3] * 0.125f;
            if (diag) {
                if (jc     > qrow0) s0 = -1e30f;
                if (jc + 1 > qrow0) s1 = -1e30f;
                if (jc     > qrow1) s2 = -1e30f;
                if (jc + 1 > qrow1) s3 = -1e30f;
            }
            sacc[nf][0] = s0; sacc[nf][1] = s1; sacc[nf][2] = s2; sacc[nf][3] = s3;
            rmax0 = fmaxf(rmax0, fmaxf(s0, s1));
            rmax1 = fmaxf(rmax1, fmaxf(s2, s3));
        }
        rmax0 = fmaxf(rmax0, __shfl_xor_sync(0xffffffffu, rmax0, 1));
        rmax0 = fmaxf(rmax0, __shfl_xor_sync(0xffffffffu, rmax0, 2));
        rmax1 = fmaxf(rmax1, __shfl_xor_sync(0xffffffffu, rmax1, 1));
        rmax1 = fmaxf(rmax1, __shfl_xor_sync(0xffffffffu, rmax1, 2));

        float mn0 = fmaxf(m0, rmax0);
        float mn1 = fmaxf(m1, rmax1);
        float alpha0 = __expf(m0 - mn0);
        float alpha1 = __expf(m1 - mn1);
        m0 = mn0; m1 = mn1;

        float rsum0 = 0.f, rsum1 = 0.f;
#pragma unroll
        for (int nf = 0; nf < 8; nf++) {
            float p0 = __expf(sacc[nf][0] - mn0);
            float p1 = __expf(sacc[nf][1] - mn0);
            float p2 = __expf(sacc[nf][2] - mn1);
            float p3 = __expf(sacc[nf][3] - mn1);
            sacc[nf][0] = p0; sacc[nf][1] = p1; sacc[nf][2] = p2; sacc[nf][3] = p3;
            rsum0 += p0 + p1;
            rsum1 += p2 + p3;
        }
        rsum0 += __shfl_xor_sync(0xffffffffu, rsum0, 1);
        rsum0 += __shfl_xor_sync(0xffffffffu, rsum0, 2);
        rsum1 += __shfl_xor_sync(0xffffffffu, rsum1, 1);
        rsum1 += __shfl_xor_sync(0xffffffffu, rsum1, 2);
        l0 = l0 * alpha0 + rsum0;
        l1 = l1 * alpha1 + rsum1;

#pragma unroll
        for (int nf = 0; nf < 8; nf++) {
            oacc[nf][0] *= alpha0; oacc[nf][1] *= alpha0;
            oacc[nf][2] *= alpha1; oacc[nf][3] *= alpha1;
        }

        // ---- stage P to smem for PV mma ----
#pragma unroll
        for (int nf = 0; nf < 8; nf++) {
            int pc = nf * 8 + 2 * lr;
            float* p0 = Ps + r0l * AT_PAD + pc;
            p0[0] = sacc[nf][0]; p0[1] = sacc[nf][1];
            float* p1 = Ps + (r0l + 8) * AT_PAD + pc;
            p1[0] = sacc[nf][2]; p1[1] = sacc[nf][3];
        }
        __syncwarp();

        // ---- O += P V ----
#pragma unroll
        for (int kf = 0; kf < 8; kf++) {
            const int kk = kf * 8 + lr;
            uint32_t a0 = FU(Ps[r0l * AT_PAD + kk]);
            uint32_t a1 = FU(Ps[(r0l + 8) * AT_PAD + kk]);
            uint32_t a2 = FU(Ps[r0l * AT_PAD + kk + 4]);
            uint32_t a3 = FU(Ps[(r0l + 8) * AT_PAD + kk + 4]);
#pragma unroll
            for (int nf = 0; nf < 8; nf++) {
                int d = nf * 8 + lq;
                uint32_t b0 = FU(Vs[(kf * 8 + lr) * AT_PAD + d]);
                uint32_t b1 = FU(Vs[(kf * 8 + lr + 4) * AT_PAD + d]);
                mma_tf32(oacc[nf], a0, a1, a2, a3, b0, b1);
            }
        }
    }

    // ---- epilogue: fp16 out ----
    float inv0 = 1.f / l0;
    float inv1 = 1.f / l1;
    int grow0 = b * S_LEN + qrow0;
    int grow1 = b * S_LEN + qrow1;
#pragma unroll
    for (int nf = 0; nf < 8; nf++) {
        int col = nf * 8 + 2 * lr;
        *(__half2*)(o + ((size_t)(grow0 * NH + h)) * HDIM + col) =
            __floats2half2_rn(oacc[nf][0] * inv0, oacc[nf][1] * inv0);
        *(__half2*)(o + ((size_t)(grow1 * NH + h)) * HDIM + col) =
            __floats2half2_rn(oacc[nf][2] * inv1, oacc[nf][3] * inv1);
    }
}

// ---------------- launch ----------------
extern "C" void kernel_launch(void* const* d_in, const int* in_sizes, int n_in,
                              void* d_out, int out_size) {
    const float* x  = (const float*)d_in[0];
    const float* Wq = (const float*)d_in[1];
    const float* Wk = (const float*)d_in[2];
    const float* Wv = (const float*)d_in[3];
    const float* Wo = (const float*)d_in[4];
    const float* an = (const float*)d_in[5];
    const float* w0 = (const float*)d_in[6];
    const float* w1 = (const float*)d_in[7];
    const float* w2 = (const float*)d_in[8];
    const float* sn = (const float*)d_in[9];
    const float* on = (const float*)d_in[10];
    float* out = (float*)d_out;

    __half *h, *q, *k, *v, *att, *gate;
    __half *hWq, *hWk, *hWv, *hWo, *hw0, *hw1, *hw2;
    float *x1, *x2, *cosT, *sinT;
    cudaGetSymbolAddress((void**)&h,    g_h);
    cudaGetSymbolAddress((void**)&q,    g_q);
    cudaGetSymbolAddress((void**)&k,    g_k);
    cudaGetSymbolAddress((void**)&v,    g_v);
    cudaGetSymbolAddress((void**)&att,  g_att);
    cudaGetSymbolAddress((void**)&gate, g_gate);
    cudaGetSymbolAddress((void**)&x1,   g_x1);
    cudaGetSymbolAddress((void**)&x2,   g_x2);
    cudaGetSymbolAddress((void**)&cosT, g_cosT);
    cudaGetSymbolAddress((void**)&sinT, g_sinT);
    cudaGetSymbolAddress((void**)&hWq,  g_hWq);
    cudaGetSymbolAddress((void**)&hWk,  g_hWk);
    cudaGetSymbolAddress((void**)&hWv,  g_hWv);
    cudaGetSymbolAddress((void**)&hWo,  g_hWo);
    cudaGetSymbolAddress((void**)&hw0,  g_hw0);
    cudaGetSymbolAddress((void**)&hw1,  g_hw1);
    cudaGetSymbolAddress((void**)&hw2,  g_hw2);

    cudaFuncSetAttribute(flash_tf32_kernel,
                         cudaFuncAttributeMaxDynamicSharedMemorySize, FLASH_SMEM);
    cudaFuncSetAttribute(gemm_f16_kernel,
                         cudaFuncAttributeMaxDynamicSharedMemorySize, GEMM_SMEM);

    rope_table_kernel<<<(S_LEN * 32 + 255) / 256, 256>>>(cosT, sinT);

    // weight convert+transpose: src [K][N] -> dst [N][K], fp16
    const dim3 tb(32, 8);
    w_t_h_kernel<<<dim3(DMODEL / 32, DMODEL / 32, NLAYER), tb>>>(Wq, hWq, DMODEL, DMODEL);
    w_t_h_kernel<<<dim3(KVD / 32,    DMODEL / 32, NLAYER), tb>>>(Wk, hWk, DMODEL, KVD);
    w_t_h_kernel<<<dim3(KVD / 32,    DMODEL / 32, NLAYER), tb>>>(Wv, hWv, DMODEL, KVD);
    w_t_h_kernel<<<dim3(DMODEL / 32, DMODEL / 32, NLAYER), tb>>>(Wo, hWo, DMODEL, DMODEL);
    w_t_h_kernel<<<dim3(FFDIM / 32,  DMODEL / 32, NLAYER), tb>>>(w0, hw0, DMODEL, FFDIM);
    w_t_h_kernel<<<dim3(FFDIM / 32,  DMODEL / 32, NLAYER), tb>>>(w1, hw1, DMODEL, FFDIM);
    w_t_h_kernel<<<dim3(DMODEL / 32, FFDIM / 32,  NLAYER), tb>>>(w2, hw2, FFDIM, DMODEL);

    const dim3 gN768(DMODEL / 128, M_TOK / 128, 1);
    const dim3 gKV  (KVD / 128,    M_TOK / 128, 2);
    const dim3 gFF  (FFDIM / 128,  M_TOK / 128, 1);

    const float* xin = x;
    for (int l = 0; l < NLAYER; l++) {
        __half* hWq_l = hWq + (size_t)l * DMODEL * DMODEL;
        __half* hWk_l = hWk + (size_t)l * KVD * DMODEL;
        __half* hWv_l = hWv + (size_t)l * KVD * DMODEL;
        __half* hWo_l = hWo + (size_t)l * DMODEL * DMODEL;
        __half* hw0_l = hw0 + (size_t)l * FFDIM * DMODEL;
        __half* hw1_l = hw1 + (size_t)l * FFDIM * DMODEL;
        __half* hw2_l = hw2 + (size_t)l * DMODEL * FFDIM;

        rmsnorm_kernel<<<M_TOK, 256>>>(xin, an + l * DMODEL, h, nullptr);
        gemm_f16_kernel<<<gN768, 256, GEMM_SMEM>>>(h, hWq_l, hWq_l, nullptr, q, q, DMODEL, DMODEL, 0);
        gemm_f16_kernel<<<gKV,   256, GEMM_SMEM>>>(h, hWk_l, hWv_l, nullptr, k, v, KVD, DMODEL, 0);
        rope_kernel<<<M_TOK, 256>>>(q, k, cosT, sinT);
        flash_tf32_kernel<<<dim3(S_LEN / 64, BATCH * NH), 128, FLASH_SMEM>>>(q, k, v, att);
        gemm_f16_kernel<<<gN768, 256, GEMM_SMEM>>>(att, hWo_l, hWo_l, xin, x1, x1, DMODEL, DMODEL, 3);
        rmsnorm_kernel<<<M_TOK, 256>>>(x1, sn + l * DMODEL, h, nullptr);
        gemm_f16_kernel<<<gFF, 256, GEMM_SMEM>>>(h, hw0_l, hw0_l, nullptr, gate, gate, FFDIM, DMODEL, 1);
        gemm_f16_kernel<<<gFF, 256, GEMM_SMEM>>>(h, hw1_l, hw1_l, gate, gate, gate, FFDIM, DMODEL, 2);
        gemm_f16_kernel<<<gN768, 256, GEMM_SMEM>>>(gate, hw2_l, hw2_l, x1, x2, x2, DMODEL, FFDIM, 3);
        xin = x2;
    }
    rmsnorm_kernel<<<M_TOK, 256>>>(x2, on, nullptr, out);
}

// round 7
// speedup vs baseline: 2.2982x; 1.2545x over previous
#include <cuda_runtime.h>
#include <cuda_fp16.h>
#include <math.h>
#include <stdint.h>

// ---------------- problem constants ----------------
#define S_LEN  2048
#define BATCH  2
#define DMODEL 768
#define NH     12
#define NKV    4
#define HDIM   64
#define FFDIM  3072
#define NLAYER 2
#define M_TOK  (BATCH * S_LEN)   // 4096 tokens
#define KVD    (NKV * HDIM)      // 256

// ---------------- scratch (device globals; no allocation allowed) ----------
__device__ __align__(16) __half g_h   [M_TOK * DMODEL];
__device__ __align__(16) __half g_q   [M_TOK * DMODEL];
__device__ __align__(16) __half g_k   [M_TOK * KVD];
__device__ __align__(16) __half g_v   [M_TOK * KVD];
__device__ __align__(16) __half g_att [M_TOK * DMODEL];
__device__ __align__(16) __half g_gate[M_TOK * FFDIM];
__device__ __align__(16) float  g_x1  [M_TOK * DMODEL];
__device__ __align__(16) float  g_x2  [M_TOK * DMODEL];
__device__ __align__(16) float  g_cosT[S_LEN * 32];
__device__ __align__(16) float  g_sinT[S_LEN * 32];
// fp16 transposed weights [N][K] per layer
__device__ __align__(16) __half g_hWq[NLAYER * DMODEL * DMODEL];
__device__ __align__(16) __half g_hWk[NLAYER * KVD * DMODEL];
__device__ __align__(16) __half g_hWv[NLAYER * KVD * DMODEL];
__device__ __align__(16) __half g_hWo[NLAYER * DMODEL * DMODEL];
__device__ __align__(16) __half g_hw0[NLAYER * FFDIM * DMODEL];
__device__ __align__(16) __half g_hw1[NLAYER * FFDIM * DMODEL];
__device__ __align__(16) __half g_hw2[NLAYER * DMODEL * FFDIM];

// ---------------- helpers ----------------
__device__ __forceinline__ void mma_f16(float (&c)[4],
                                        uint32_t a0, uint32_t a1, uint32_t a2, uint32_t a3,
                                        uint32_t b0, uint32_t b1) {
    asm volatile(
        "mma.sync.aligned.m16n8k16.row.col.f32.f16.f16.f32 "
        "{%0,%1,%2,%3}, {%4,%5,%6,%7}, {%8,%9}, {%0,%1,%2,%3};"
        : "+f"(c[0]), "+f"(c[1]), "+f"(c[2]), "+f"(c[3])
        : "r"(a0), "r"(a1), "r"(a2), "r"(a3), "r"(b0), "r"(b1));
}
__device__ __forceinline__ void cpa16(uint32_t d, const void* s) {
    asm volatile("cp.async.cg.shared.global [%0], [%1], 16;" :: "r"(d), "l"(s));
}
__device__ __forceinline__ void cpcommit() { asm volatile("cp.async.commit_group;"); }
__device__ __forceinline__ void cpwait1()  { asm volatile("cp.async.wait_group 1;"); }
__device__ __forceinline__ void cpwait0()  { asm volatile("cp.async.wait_group 0;"); }

// ---------------- RoPE tables ----------------
__global__ void rope_table_kernel(float* __restrict__ cosT, float* __restrict__ sinT) {
    int idx = blockIdx.x * blockDim.x + threadIdx.x;
    if (idx >= S_LEN * 32) return;
    int p = idx >> 5, i = idx & 31;
    double f  = exp(-((double)(2 * i) / 64.0) * log(10000.0));
    float ang = (float)p * (float)f;
    cosT[idx] = (float)cos((double)ang);
    sinT[idx] = (float)sin((double)ang);
}

// ---------------- weight transpose + fp16 convert: src[K][N] -> dst[N][K] --
__global__ void w_t_h_kernel(const float* __restrict__ src, __half* __restrict__ dst,
                             int K, int N) {
    __shared__ float tile[32][33];
    int l = blockIdx.z;
    src += (size_t)l * K * N;
    dst += (size_t)l * K * N;
    int nb = blockIdx.x * 32, kb = blockIdx.y * 32;
    int tx = threadIdx.x, ty = threadIdx.y;   // 32 x 8
#pragma unroll
    for (int i = 0; i < 4; i++)
        tile[ty + 8 * i][tx] = src[(size_t)(kb + ty + 8 * i) * N + nb + tx];
    __syncthreads();
#pragma unroll
    for (int i = 0; i < 4; i++)
        dst[(size_t)(nb + ty + 8 * i) * K + kb + tx] = __float2half_rn(tile[tx][ty + 8 * i]);
}

// ---------------- RMSNorm (fp32 in -> fp16 out, or fp32 out if oh==null) ---
__global__ void rmsnorm_kernel(const float* __restrict__ x,
                               const float* __restrict__ w,
                               __half* __restrict__ oh,
                               float* __restrict__ of) {
    int row = blockIdx.x;
    const float* xr = x + (size_t)row * DMODEL;
    float v[3];
    float s = 0.f;
#pragma unroll
    for (int t = 0; t < 3; t++) {
        v[t] = xr[threadIdx.x + t * 256];
        s += v[t] * v[t];
    }
#pragma unroll
    for (int off = 16; off > 0; off >>= 1) s += __shfl_xor_sync(0xffffffffu, s, off);
    __shared__ float red[8];
    if ((threadIdx.x & 31) == 0) red[threadIdx.x >> 5] = s;
    __syncthreads();
    float tot = 0.f;
#pragma unroll
    for (int i = 0; i < 8; i++) tot += red[i];
    float scale = rsqrtf(tot * (1.0f / (float)DMODEL) + 1e-6f);
    if (oh) {
        __half* orow = oh + (size_t)row * DMODEL;
#pragma unroll
        for (int t = 0; t < 3; t++) {
            int c = threadIdx.x + t * 256;
            orow[c] = __float2half_rn(v[t] * scale * w[c]);
        }
    } else {
        float* orow = of + (size_t)row * DMODEL;
#pragma unroll
        for (int t = 0; t < 3; t++) {
            int c = threadIdx.x + t * 256;
            orow[c] = v[t] * scale * w[c];
        }
    }
}

// ---------------- RoPE apply on fp16 q/k (one block per token) -------------
__global__ void rope_kernel(__half* __restrict__ q, __half* __restrict__ k,
                            const float* __restrict__ cosT,
                            const float* __restrict__ sinT) {
    int token = blockIdx.x;
    int pos = token & (S_LEN - 1);
    for (int t = threadIdx.x; t < (NH + NKV) * 32; t += 256) {
        int i  = t & 31;
        int hh = t >> 5;   // 0..11 = q heads, 12..15 = k heads
        float c = cosT[pos * 32 + i];
        float s = sinT[pos * 32 + i];
        __half2* base = (hh < NH)
            ? (__half2*)(q + (size_t)token * DMODEL + hh * HDIM)
            : (__half2*)(k + (size_t)token * KVD + (hh - NH) * HDIM);
        __half2 p = base[i];
        float t0 = __low2float(p), t1 = __high2float(p);
        base[i] = __floats2half2_rn(t0 * c - t1 * s, t0 * s + t1 * c);
    }
}

// ---------------- FP16 tensor-core GEMM, tile 128x128x32, cp.async 3-stage -
#define KT   32
#define STG  3
#define AST  40
#define BST  40
#define GEMM_SMEM ((STG * 128 * AST + STG * 128 * BST) * 2)   // 61440 bytes

__global__ void __launch_bounds__(256, 2) gemm_f16_kernel(
    const __half* __restrict__ A,
    const __half* __restrict__ B0t, const __half* __restrict__ B1t,
    const void* __restrict__ aux,
    void* __restrict__ O0, void* __restrict__ O1,
    int N, int K, int mode) {
    const __half* Bt = blockIdx.z ? B1t : B0t;
    void*         O  = blockIdx.z ? O1 : O0;
    extern __shared__ __half sm[];
    __half* Asm = sm;
    __half* Bsm = sm + STG * 128 * AST;
    uint32_t aBase = (uint32_t)__cvta_generic_to_shared(Asm);
    uint32_t bBase = (uint32_t)__cvta_generic_to_shared(Bsm);

    const int tid  = threadIdx.x;
    const int lane = tid & 31;
    const int warp = tid >> 5;
    const int wm   = warp & 1;
    const int wn   = warp >> 1;
    const int rowBase = blockIdx.y * 128;
    const int colBase = blockIdx.x * 128;
    const int lq = lane >> 2;
    const int lr = lane & 3;

    float acc[4][4][4];
#pragma unroll
    for (int i = 0; i < 4; i++)
#pragma unroll
        for (int j = 0; j < 4; j++)
#pragma unroll
            for (int t = 0; t < 4; t++) acc[i][j][t] = 0.f;

    const int T = K / KT;

    auto stage = [&](int s, int kt) {
#pragma unroll
        for (int c0 = 0; c0 < 2; c0++) {
            int c = tid + c0 * 256;
            int r = c >> 2, k8 = (c & 3) * 8;
            cpa16(aBase + (uint32_t)(s * 128 * AST + r * AST + k8) * 2,
                  A  + (size_t)(rowBase + r) * K + kt * KT + k8);
            cpa16(bBase + (uint32_t)(s * 128 * BST + r * BST + k8) * 2,
                  Bt + (size_t)(colBase + r) * K + kt * KT + k8);
        }
    };

    stage(0, 0); cpcommit();
    stage(1, 1); cpcommit();

    for (int t = 0; t < T; t++) {
        cpwait1();
        __syncthreads();
        if (t + 2 < T) stage((t + 2) % STG, t + 2);
        cpcommit();

        const __half* Ab = Asm + (t % STG) * 128 * AST;
        const __half* Bb = Bsm + (t % STG) * 128 * BST;
#pragma unroll
        for (int kf = 0; kf < 2; kf++) {
            const int k0 = kf * 16;
            uint32_t af[4][4];
#pragma unroll
            for (int mf = 0; mf < 4; mf++) {
                int r0 = wm * 64 + mf * 16 + lq;
                af[mf][0] = *(const uint32_t*)(Ab + r0 * AST + k0 + 2 * lr);
                af[mf][1] = *(const uint32_t*)(Ab + (r0 + 8) * AST + k0 + 2 * lr);
                af[mf][2] = *(const uint32_t*)(Ab + r0 * AST + k0 + 8 + 2 * lr);
                af[mf][3] = *(const uint32_t*)(Ab + (r0 + 8) * AST + k0 + 8 + 2 * lr);
            }
#pragma unroll
            for (int nf = 0; nf < 4; nf++) {
                int c0 = wn * 32 + nf * 8 + lq;
                uint32_t b0 = *(const uint32_t*)(Bb + c0 * BST + k0 + 2 * lr);
                uint32_t b1 = *(const uint32_t*)(Bb + c0 * BST + k0 + 8 + 2 * lr);
#pragma unroll
                for (int mf = 0; mf < 4; mf++)
                    mma_f16(acc[mf][nf], af[mf][0], af[mf][1], af[mf][2], af[mf][3], b0, b1);
            }
        }
    }
    __syncthreads();

#pragma unroll
    for (int mf = 0; mf < 4; mf++) {
        int row0 = rowBase + wm * 64 + mf * 16 + lq;
#pragma unroll
        for (int nf = 0; nf < 4; nf++) {
            int col = colBase + wn * 32 + nf * 8 + 2 * lr;
#pragma unroll
            for (int hh = 0; hh < 2; hh++) {
                int row = row0 + hh * 8;
                size_t idx = (size_t)row * N + col;
                float v0 = acc[mf][nf][hh * 2];
                float v1 = acc[mf][nf][hh * 2 + 1];
                if (mode == 3) {
                    float2 a2 = *(const float2*)((const float*)aux + idx);
                    *(float2*)((float*)O + idx) = make_float2(v0 + a2.x, v1 + a2.y);
                } else {
                    if (mode == 1) {
                        v0 = v0 / (1.f + __expf(-v0));
                        v1 = v1 / (1.f + __expf(-v1));
                    } else if (mode == 2) {
                        __half2 g2 = *(const __half2*)((const __half*)aux + idx);
                        v0 *= __low2float(g2);
                        v1 *= __high2float(g2);
                    }
                    *(__half2*)((__half*)O + idx) = __floats2half2_rn(v0, v1);
                }
            }
        }
    }
}

// ---------------- Flash attention, FP16 mma (causal, GQA), cp.async K/V ----
#define VST 72
#define FLASH_SMEM (6 * 64 * VST * 2)   // Qh + 2*Kh + 2*Vh + Ph = 55296 B

__global__ void __launch_bounds__(128) flash_f16_kernel(
    const __half* __restrict__ q, const __half* __restrict__ k,
    const __half* __restrict__ v, __half* __restrict__ o) {
    extern __shared__ __half smh[];
    __half* Qh = smh;                   // [64][VST]
    __half* Kh = smh + 64 * VST;        // 2 bufs
    __half* Vh = smh + 3 * 64 * VST;    // 2 bufs
    __half* Ph = smh + 5 * 64 * VST;
    uint32_t kBase = (uint32_t)__cvta_generic_to_shared(Kh);
    uint32_t vBase = (uint32_t)__cvta_generic_to_shared(Vh);

    const int qb  = (gridDim.x - 1) - blockIdx.x;   // heavy blocks first
    const int bh  = blockIdx.y;
    const int b   = bh / NH;
    const int h   = bh % NH;
    const int kvh = h / (NH / NKV);
    const int tid  = threadIdx.x;
    const int lane = tid & 31;
    const int warp = tid >> 5;
    const int lq = lane >> 2;
    const int lr = lane & 3;

    // load Q tile [64 x 64] (raw half copy)
    for (int t = tid; t < 64 * 8; t += 128) {
        int r = t >> 3, c8 = (t & 7) * 8;
        uint4 raw = *(const uint4*)(q + ((size_t)((b * S_LEN + qb * 64 + r) * NH + h)) * HDIM + c8);
        *(uint4*)(Qh + r * VST + c8) = raw;
    }

    auto stageKV = [&](int buf, int kb) {
        for (int t = tid; t < 64 * 8; t += 128) {
            int r = t >> 3, c8 = (t & 7) * 8;
            size_t goff = ((size_t)((b * S_LEN + kb * 64 + r) * NKV + kvh)) * HDIM + c8;
            uint32_t soff = (uint32_t)(buf * 64 * VST + r * VST + c8) * 2;
            cpa16(kBase + soff, k + goff);
            cpa16(vBase + soff, v + goff);
        }
    };
    stageKV(0, 0); cpcommit();

    const int r0l = warp * 16 + lq;
    const int qrow0 = qb * 64 + r0l;
    const int qrow1 = qrow0 + 8;

    float m0 = -1e30f, m1 = -1e30f, l0 = 0.f, l1 = 0.f;
    float oacc[8][4];
#pragma unroll
    for (int nf = 0; nf < 8; nf++)
#pragma unroll
        for (int t = 0; t < 4; t++) oacc[nf][t] = 0.f;

    for (int kb = 0; kb <= qb; kb++) {
        const int buf = kb & 1;
        cpwait0();
        __syncthreads();   // K/V(buf) landed; all warps done with buf^1
        if (kb + 1 <= qb) { stageKV(buf ^ 1, kb + 1); cpcommit(); }

        const __half* Kb = Kh + buf * 64 * VST;
        const __half* Vb = Vh + buf * 64 * VST;

        // ---- S = Q K^T (fp16 mma) ----
        float sacc[8][4];
#pragma unroll
        for (int nf = 0; nf < 8; nf++)
#pragma unroll
            for (int t = 0; t < 4; t++) sacc[nf][t] = 0.f;

#pragma unroll
        for (int kf = 0; kf < 4; kf++) {
            const int k0 = kf * 16;
            uint32_t a0 = *(const uint32_t*)(Qh + r0l * VST + k0 + 2 * lr);
            uint32_t a1 = *(const uint32_t*)(Qh + (r0l + 8) * VST + k0 + 2 * lr);
            uint32_t a2 = *(const uint32_t*)(Qh + r0l * VST + k0 + 8 + 2 * lr);
            uint32_t a3 = *(const uint32_t*)(Qh + (r0l + 8) * VST + k0 + 8 + 2 * lr);
#pragma unroll
            for (int nf = 0; nf < 8; nf++) {
                const __half* kr = Kb + (nf * 8 + lq) * VST + k0;
                uint32_t b0 = *(const uint32_t*)(kr + 2 * lr);
                uint32_t b1 = *(const uint32_t*)(kr + 8 + 2 * lr);
                mma_f16(sacc[nf], a0, a1, a2, a3, b0, b1);
            }
        }

        // ---- scale, mask, online softmax ----
        const bool diag = (kb == qb);
        float rmax0 = -1e30f, rmax1 = -1e30f;
#pragma unroll
        for (int nf = 0; nf < 8; nf++) {
            int jc = kb * 64 + nf * 8 + 2 * lr;
            float s0 = sacc[nf][0] * 0.125f;
            float s1 = sacc[nf][1] * 0.125f;
            float s2 = sacc[nf][2] * 0.125f;
            float s3 = sacc[nf][3] * 0.125f;
            if (diag) {
                if (jc     > qrow0) s0 = -1e30f;
                if (jc + 1 > qrow0) s1 = -1e30f;
                if (jc     > qrow1) s2 = -1e30f;
                if (jc + 1 > qrow1) s3 = -1e30f;
            }
            sacc[nf][0] = s0; sacc[nf][1] = s1; sacc[nf][2] = s2; sacc[nf][3] = s3;
            rmax0 = fmaxf(rmax0, fmaxf(s0, s1));
            rmax1 = fmaxf(rmax1, fmaxf(s2, s3));
        }
        rmax0 = fmaxf(rmax0, __shfl_xor_sync(0xffffffffu, rmax0, 1));
        rmax0 = fmaxf(rmax0, __shfl_xor_sync(0xffffffffu, rmax0, 2));
        rmax1 = fmaxf(rmax1, __shfl_xor_sync(0xffffffffu, rmax1, 1));
        rmax1 = fmaxf(rmax1, __shfl_xor_sync(0xffffffffu, rmax1, 2));

        float mn0 = fmaxf(m0, rmax0);
        float mn1 = fmaxf(m1, rmax1);
        float alpha0 = __expf(m0 - mn0);
        float alpha1 = __expf(m1 - mn1);
        m0 = mn0; m1 = mn1;

        float rsum0 = 0.f, rsum1 = 0.f;
#pragma unroll
        for (int nf = 0; nf < 8; nf++) {
            float p0 = __expf(sacc[nf][0] - mn0);
            float p1 = __expf(sacc[nf][1] - mn0);
            float p2 = __expf(sacc[nf][2] - mn1);
            float p3 = __expf(sacc[nf][3] - mn1);
            sacc[nf][0] = p0; sacc[nf][1] = p1; sacc[nf][2] = p2; sacc[nf][3] = p3;
            rsum0 += p0 + p1;
            rsum1 += p2 + p3;
        }
        rsum0 += __shfl_xor_sync(0xffffffffu, rsum0, 1);
        rsum0 += __shfl_xor_sync(0xffffffffu, rsum0, 2);
        rsum1 += __shfl_xor_sync(0xffffffffu, rsum1, 1);
        rsum1 += __shfl_xor_sync(0xffffffffu, rsum1, 2);
        l0 = l0 * alpha0 + rsum0;
        l1 = l1 * alpha1 + rsum1;

#pragma unroll
        for (int nf = 0; nf < 8; nf++) {
            oacc[nf][0] *= alpha0; oacc[nf][1] *= alpha0;
            oacc[nf][2] *= alpha1; oacc[nf][3] *= alpha1;
        }

        // ---- stage P (half) to smem ----
#pragma unroll
        for (int nf = 0; nf < 8; nf++) {
            int pc = nf * 8 + 2 * lr;
            *(__half2*)(Ph + r0l * VST + pc)       = __floats2half2_rn(sacc[nf][0], sacc[nf][1]);
            *(__half2*)(Ph + (r0l + 8) * VST + pc) = __floats2half2_rn(sacc[nf][2], sacc[nf][3]);
        }
        __syncwarp();

        // ---- O += P V  (V^T fragments via ldmatrix.trans) ----
        const uint32_t vTileBase = vBase + (uint32_t)(buf * 64 * VST) * 2;
#pragma unroll
        for (int kf = 0; kf < 4; kf++) {
            const int k0 = kf * 16;
            uint32_t a0 = *(const uint32_t*)(Ph + r0l * VST + k0 + 2 * lr);
            uint32_t a1 = *(const uint32_t*)(Ph + (r0l + 8) * VST + k0 + 2 * lr);
            uint32_t a2 = *(const uint32_t*)(Ph + r0l * VST + k0 + 8 + 2 * lr);
            uint32_t a3 = *(const uint32_t*)(Ph + (r0l + 8) * VST + k0 + 8 + 2 * lr);
#pragma unroll
            for (int np = 0; np < 4; np++) {
                const int d0 = np * 16;
                uint32_t addr = vTileBase +
                    (uint32_t)((k0 + (lane & 15)) * VST + d0 + ((lane & 16) >> 1)) * 2;
                uint32_t bb0, bb1, bb2, bb3;
                asm volatile(
                    "ldmatrix.sync.aligned.m8n8.x4.trans.shared.b16 {%0,%1,%2,%3}, [%4];"
                    : "=r"(bb0), "=r"(bb1), "=r"(bb2), "=r"(bb3) : "r"(addr));
                mma_f16(oacc[2 * np],     a0, a1, a2, a3, bb0, bb1);
                mma_f16(oacc[2 * np + 1], a0, a1, a2, a3, bb2, bb3);
            }
        }
    }

    // ---- epilogue: fp16 out ----
    float inv0 = 1.f / l0;
    float inv1 = 1.f / l1;
    int grow0 = b * S_LEN + qrow0;
    int grow1 = b * S_LEN + qrow1;
#pragma unroll
    for (int nf = 0; nf < 8; nf++) {
        int col = nf * 8 + 2 * lr;
        *(__half2*)(o + ((size_t)(grow0 * NH + h)) * HDIM + col) =
            __floats2half2_rn(oacc[nf][0] * inv0, oacc[nf][1] * inv0);
        *(__half2*)(o + ((size_t)(grow1 * NH + h)) * HDIM + col) =
            __floats2half2_rn(oacc[nf][2] * inv1, oacc[nf][3] * inv1);
    }
}

// ---------------- launch ----------------
extern "C" void kernel_launch(void* const* d_in, const int* in_sizes, int n_in,
                              void* d_out, int out_size) {
    const float* x  = (const float*)d_in[0];
    const float* Wq = (const float*)d_in[1];
    const float* Wk = (const float*)d_in[2];
    const float* Wv = (const float*)d_in[3];
    const float* Wo = (const float*)d_in[4];
    const float* an = (const float*)d_in[5];
    const float* w0 = (const float*)d_in[6];
    const float* w1 = (const float*)d_in[7];
    const float* w2 = (const float*)d_in[8];
    const float* sn = (const float*)d_in[9];
    const float* on = (const float*)d_in[10];
    float* out = (float*)d_out;

    __half *h, *q, *k, *v, *att, *gate;
    __half *hWq, *hWk, *hWv, *hWo, *hw0, *hw1, *hw2;
    float *x1, *x2, *cosT, *sinT;
    cudaGetSymbolAddress((void**)&h,    g_h);
    cudaGetSymbolAddress((void**)&q,    g_q);
    cudaGetSymbolAddress((void**)&k,    g_k);
    cudaGetSymbolAddress((void**)&v,    g_v);
    cudaGetSymbolAddress((void**)&att,  g_att);
    cudaGetSymbolAddress((void**)&gate, g_gate);
    cudaGetSymbolAddress((void**)&x1,   g_x1);
    cudaGetSymbolAddress((void**)&x2,   g_x2);
    cudaGetSymbolAddress((void**)&cosT, g_cosT);
    cudaGetSymbolAddress((void**)&sinT, g_sinT);
    cudaGetSymbolAddress((void**)&hWq,  g_hWq);
    cudaGetSymbolAddress((void**)&hWk,  g_hWk);
    cudaGetSymbolAddress((void**)&hWv,  g_hWv);
    cudaGetSymbolAddress((void**)&hWo,  g_hWo);
    cudaGetSymbolAddress((void**)&hw0,  g_hw0);
    cudaGetSymbolAddress((void**)&hw1,  g_hw1);
    cudaGetSymbolAddress((void**)&hw2,  g_hw2);

    cudaFuncSetAttribute(flash_f16_kernel,
                         cudaFuncAttributeMaxDynamicSharedMemorySize, FLASH_SMEM);
    cudaFuncSetAttribute(gemm_f16_kernel,
                         cudaFuncAttributeMaxDynamicSharedMemorySize, GEMM_SMEM);

    rope_table_kernel<<<(S_LEN * 32 + 255) / 256, 256>>>(cosT, sinT);

    const dim3 tb(32, 8);
    w_t_h_kernel<<<dim3(DMODEL / 32, DMODEL / 32, NLAYER), tb>>>(Wq, hWq, DMODEL, DMODEL);
    w_t_h_kernel<<<dim3(KVD / 32,    DMODEL / 32, NLAYER), tb>>>(Wk, hWk, DMODEL, KVD);
    w_t_h_kernel<<<dim3(KVD / 32,    DMODEL / 32, NLAYER), tb>>>(Wv, hWv, DMODEL, KVD);
    w_t_h_kernel<<<dim3(DMODEL / 32, DMODEL / 32, NLAYER), tb>>>(Wo, hWo, DMODEL, DMODEL);
    w_t_h_kernel<<<dim3(FFDIM / 32,  DMODEL / 32, NLAYER), tb>>>(w0, hw0, DMODEL, FFDIM);
    w_t_h_kernel<<<dim3(FFDIM / 32,  DMODEL / 32, NLAYER), tb>>>(w1, hw1, DMODEL, FFDIM);
    w_t_h_kernel<<<dim3(DMODEL / 32, FFDIM / 32,  NLAYER), tb>>>(w2, hw2, FFDIM, DMODEL);

    const dim3 gN768(DMODEL / 128, M_TOK / 128, 1);
    const dim3 gKV  (KVD / 128,    M_TOK / 128, 2);
    const dim3 gFF  (FFDIM / 128,  M_TOK / 128, 1);

    const float* xin = x;
    for (int l = 0; l < NLAYER; l++) {
        __half* hWq_l = hWq + (size_t)l * DMODEL * DMODEL;
        __half* hWk_l = hWk + (size_t)l * KVD * DMODEL;
        __half* hWv_l = hWv + (size_t)l * KVD * DMODEL;
        __half* hWo_l = hWo + (size_t)l * DMODEL * DMODEL;
        __half* hw0_l = hw0 + (size_t)l * FFDIM * DMODEL;
        __half* hw1_l = hw1 + (size_t)l * FFDIM * DMODEL;
        __half* hw2_l = hw2 + (size_t)l * DMODEL * FFDIM;

        rmsnorm_kernel<<<M_TOK, 256>>>(xin, an + l * DMODEL, h, nullptr);
        gemm_f16_kernel<<<gN768, 256, GEMM_SMEM>>>(h, hWq_l, hWq_l, nullptr, q, q, DMODEL, DMODEL, 0);
        gemm_f16_kernel<<<gKV,   256, GEMM_SMEM>>>(h, hWk_l, hWv_l, nullptr, k, v, KVD, DMODEL, 0);
        rope_kernel<<<M_TOK, 256>>>(q, k, cosT, sinT);
        flash_f16_kernel<<<dim3(S_LEN / 64, BATCH * NH), 128, FLASH_SMEM>>>(q, k, v, att);
        gemm_f16_kernel<<<gN768, 256, GEMM_SMEM>>>(att, hWo_l, hWo_l, xin, x1, x1, DMODEL, DMODEL, 3);
        rmsnorm_kernel<<<M_TOK, 256>>>(x1, sn + l * DMODEL, h, nullptr);
        gemm_f16_kernel<<<gFF, 256, GEMM_SMEM>>>(h, hw0_l, hw0_l, nullptr, gate, gate, FFDIM, DMODEL, 1);
        gemm_f16_kernel<<<gFF, 256, GEMM_SMEM>>>(h, hw1_l, hw1_l, gate, gate, gate, FFDIM, DMODEL, 2);
        gemm_f16_kernel<<<gN768, 256, GEMM_SMEM>>>(gate, hw2_l, hw2_l, x1, x2, x2, DMODEL, FFDIM, 3);
        xin = x2;
    }
    rmsnorm_kernel<<<M_TOK, 256>>>(x2, on, nullptr, out);
}

// round 8
// speedup vs baseline: 2.5257x; 1.0990x over previous
#include <cuda_runtime.h>
#include <cuda_fp16.h>
#include <math.h>
#include <stdint.h>

// ---------------- problem constants ----------------
#define S_LEN  2048
#define BATCH  2
#define DMODEL 768
#define NH     12
#define NKV    4
#define HDIM   64
#define FFDIM  3072
#define NLAYER 2
#define M_TOK  (BATCH * S_LEN)   // 4096 tokens
#define KVD    (NKV * HDIM)      // 256

// ---------------- scratch (device globals; no allocation allowed) ----------
__device__ __align__(16) __half g_h   [M_TOK * DMODEL];
__device__ __align__(16) __half g_q   [M_TOK * DMODEL];
__device__ __align__(16) __half g_k   [M_TOK * KVD];
__device__ __align__(16) __half g_v   [M_TOK * KVD];
__device__ __align__(16) __half g_att [M_TOK * DMODEL];
__device__ __align__(16) __half g_gate[M_TOK * FFDIM];
__device__ __align__(16) float  g_x1  [M_TOK * DMODEL];
__device__ __align__(16) float  g_x2  [M_TOK * DMODEL];
__device__ __align__(16) float  g_cosT[S_LEN * 32];
__device__ __align__(16) float  g_sinT[S_LEN * 32];
// fp16 transposed weights [N][K] per layer
__device__ __align__(16) __half g_hWq[NLAYER * DMODEL * DMODEL];
__device__ __align__(16) __half g_hWk[NLAYER * KVD * DMODEL];
__device__ __align__(16) __half g_hWv[NLAYER * KVD * DMODEL];
__device__ __align__(16) __half g_hWo[NLAYER * DMODEL * DMODEL];
__device__ __align__(16) __half g_hw0[NLAYER * FFDIM * DMODEL];
__device__ __align__(16) __half g_hw1[NLAYER * FFDIM * DMODEL];
__device__ __align__(16) __half g_hw2[NLAYER * DMODEL * FFDIM];

// ---------------- helpers ----------------
__device__ __forceinline__ void mma_f16(float (&c)[4],
                                        uint32_t a0, uint32_t a1, uint32_t a2, uint32_t a3,
                                        uint32_t b0, uint32_t b1) {
    asm volatile(
        "mma.sync.aligned.m16n8k16.row.col.f32.f16.f16.f32 "
        "{%0,%1,%2,%3}, {%4,%5,%6,%7}, {%8,%9}, {%0,%1,%2,%3};"
        : "+f"(c[0]), "+f"(c[1]), "+f"(c[2]), "+f"(c[3])
        : "r"(a0), "r"(a1), "r"(a2), "r"(a3), "r"(b0), "r"(b1));
}
__device__ __forceinline__ void ldsm_x4(uint32_t& r0, uint32_t& r1,
                                        uint32_t& r2, uint32_t& r3, uint32_t addr) {
    asm volatile("ldmatrix.sync.aligned.m8n8.x4.shared.b16 {%0,%1,%2,%3}, [%4];"
                 : "=r"(r0), "=r"(r1), "=r"(r2), "=r"(r3) : "r"(addr));
}
__device__ __forceinline__ void cpa16(uint32_t d, const void* s) {
    asm volatile("cp.async.cg.shared.global [%0], [%1], 16;" :: "r"(d), "l"(s));
}
__device__ __forceinline__ void cpcommit() { asm volatile("cp.async.commit_group;"); }
__device__ __forceinline__ void cpwait1()  { asm volatile("cp.async.wait_group 1;"); }
__device__ __forceinline__ void cpwait0()  { asm volatile("cp.async.wait_group 0;"); }

// ---------------- RoPE tables ----------------
__global__ void rope_table_kernel(float* __restrict__ cosT, float* __restrict__ sinT) {
    int idx = blockIdx.x * blockDim.x + threadIdx.x;
    if (idx >= S_LEN * 32) return;
    int p = idx >> 5, i = idx & 31;
    double f  = exp(-((double)(2 * i) / 64.0) * log(10000.0));
    float ang = (float)p * (float)f;
    cosT[idx] = (float)cos((double)ang);
    sinT[idx] = (float)sin((double)ang);
}

// ---------------- weight transpose + fp16 convert: src[K][N] -> dst[N][K] --
__global__ void w_t_h_kernel(const float* __restrict__ src, __half* __restrict__ dst,
                             int K, int N) {
    __shared__ float tile[32][33];
    int l = blockIdx.z;
    src += (size_t)l * K * N;
    dst += (size_t)l * K * N;
    int nb = blockIdx.x * 32, kb = blockIdx.y * 32;
    int tx = threadIdx.x, ty = threadIdx.y;   // 32 x 8
#pragma unroll
    for (int i = 0; i < 4; i++)
        tile[ty + 8 * i][tx] = src[(size_t)(kb + ty + 8 * i) * N + nb + tx];
    __syncthreads();
#pragma unroll
    for (int i = 0; i < 4; i++)
        dst[(size_t)(nb + ty + 8 * i) * K + kb + tx] = __float2half_rn(tile[tx][ty + 8 * i]);
}

// ---------------- RMSNorm (fp32 in -> fp16 out, or fp32 out if oh==null) ---
__global__ void rmsnorm_kernel(const float* __restrict__ x,
                               const float* __restrict__ w,
                               __half* __restrict__ oh,
                               float* __restrict__ of) {
    int row = blockIdx.x;
    const float* xr = x + (size_t)row * DMODEL;
    float v[3];
    float s = 0.f;
#pragma unroll
    for (int t = 0; t < 3; t++) {
        v[t] = xr[threadIdx.x + t * 256];
        s += v[t] * v[t];
    }
#pragma unroll
    for (int off = 16; off > 0; off >>= 1) s += __shfl_xor_sync(0xffffffffu, s, off);
    __shared__ float red[8];
    if ((threadIdx.x & 31) == 0) red[threadIdx.x >> 5] = s;
    __syncthreads();
    float tot = 0.f;
#pragma unroll
    for (int i = 0; i < 8; i++) tot += red[i];
    float scale = rsqrtf(tot * (1.0f / (float)DMODEL) + 1e-6f);
    if (oh) {
        __half* orow = oh + (size_t)row * DMODEL;
#pragma unroll
        for (int t = 0; t < 3; t++) {
            int c = threadIdx.x + t * 256;
            orow[c] = __float2half_rn(v[t] * scale * w[c]);
        }
    } else {
        float* orow = of + (size_t)row * DMODEL;
#pragma unroll
        for (int t = 0; t < 3; t++) {
            int c = threadIdx.x + t * 256;
            orow[c] = v[t] * scale * w[c];
        }
    }
}

// ---------------- RoPE apply on fp16 q/k (one block per token) -------------
__global__ void rope_kernel(__half* __restrict__ q, __half* __restrict__ k,
                            const float* __restrict__ cosT,
                            const float* __restrict__ sinT) {
    int token = blockIdx.x;
    int pos = token & (S_LEN - 1);
    for (int t = threadIdx.x; t < (NH + NKV) * 32; t += 256) {
        int i  = t & 31;
        int hh = t >> 5;
        float c = cosT[pos * 32 + i];
        float s = sinT[pos * 32 + i];
        __half2* base = (hh < NH)
            ? (__half2*)(q + (size_t)token * DMODEL + hh * HDIM)
            : (__half2*)(k + (size_t)token * KVD + (hh - NH) * HDIM);
        __half2 p = base[i];
        float t0 = __low2float(p), t1 = __high2float(p);
        base[i] = __floats2half2_rn(t0 * c - t1 * s, t0 * s + t1 * c);
    }
}

// ---------------- FP16 tensor-core GEMM, tile 128x128x32, cp.async 3-stage -
#define KT   32
#define STG  3
#define AST  40
#define BST  40
#define GEMM_SMEM ((STG * 128 * AST + STG * 128 * BST) * 2)   // 61440 bytes

__global__ void __launch_bounds__(256, 2) gemm_f16_kernel(
    const __half* __restrict__ A,
    const __half* __restrict__ B0t, const __half* __restrict__ B1t,
    const void* __restrict__ aux,
    void* __restrict__ O0, void* __restrict__ O1,
    int N, int K, int mode) {
    const __half* Bt = blockIdx.z ? B1t : B0t;
    void*         O  = blockIdx.z ? O1 : O0;
    extern __shared__ __half sm[];
    __half* Asm = sm;
    __half* Bsm = sm + STG * 128 * AST;
    uint32_t aBase = (uint32_t)__cvta_generic_to_shared(Asm);
    uint32_t bBase = (uint32_t)__cvta_generic_to_shared(Bsm);

    const int tid  = threadIdx.x;
    const int lane = tid & 31;
    const int warp = tid >> 5;
    const int wm   = warp & 1;
    const int wn   = warp >> 1;
    const int rowBase = blockIdx.y * 128;
    const int colBase = blockIdx.x * 128;
    const int lq = lane >> 2;
    const int lr = lane & 3;

    float acc[4][4][4];
#pragma unroll
    for (int i = 0; i < 4; i++)
#pragma unroll
        for (int j = 0; j < 4; j++)
#pragma unroll
            for (int t = 0; t < 4; t++) acc[i][j][t] = 0.f;

    const int T = K / KT;

    auto stage = [&](int s, int kt) {
#pragma unroll
        for (int c0 = 0; c0 < 2; c0++) {
            int c = tid + c0 * 256;
            int r = c >> 2, k8 = (c & 3) * 8;
            cpa16(aBase + (uint32_t)(s * 128 * AST + r * AST + k8) * 2,
                  A  + (size_t)(rowBase + r) * K + kt * KT + k8);
            cpa16(bBase + (uint32_t)(s * 128 * BST + r * BST + k8) * 2,
                  Bt + (size_t)(colBase + r) * K + kt * KT + k8);
        }
    };

    stage(0, 0); cpcommit();
    stage(1, 1); cpcommit();

    // per-thread ldmatrix address components
    const int aRowSel = lane & 15;          // A: 16 rows
    const int aKSel   = (lane >> 4) << 3;   // A: k0 or k0+8
    const int bRowSel = (lane & 7) + ((lane >> 4) << 3);  // B: n within 16-block
    const int bKSel   = ((lane >> 3) & 1) << 3;           // B: k0 or k0+8

    for (int t = 0; t < T; t++) {
        cpwait1();
        __syncthreads();
        if (t + 2 < T) stage((t + 2) % STG, t + 2);
        cpcommit();

        const uint32_t aTile = aBase + (uint32_t)((t % STG) * 128 * AST) * 2;
        const uint32_t bTile = bBase + (uint32_t)((t % STG) * 128 * BST) * 2;
#pragma unroll
        for (int kf = 0; kf < 2; kf++) {
            const int k0 = kf * 16;
            uint32_t af[4][4];
#pragma unroll
            for (int mf = 0; mf < 4; mf++) {
                int r0 = wm * 64 + mf * 16;
                uint32_t addr = aTile + (uint32_t)((r0 + aRowSel) * AST + k0 + aKSel) * 2;
                ldsm_x4(af[mf][0], af[mf][1], af[mf][2], af[mf][3], addr);
            }
#pragma unroll
            for (int ng = 0; ng < 2; ng++) {
                int c0 = wn * 32 + ng * 16;
                uint32_t b0, b1, b2, b3;
                uint32_t addr = bTile + (uint32_t)((c0 + bRowSel) * BST + k0 + bKSel) * 2;
                ldsm_x4(b0, b1, b2, b3, addr);
#pragma unroll
                for (int mf = 0; mf < 4; mf++) {
                    mma_f16(acc[mf][2 * ng],     af[mf][0], af[mf][1], af[mf][2], af[mf][3], b0, b1);
                    mma_f16(acc[mf][2 * ng + 1], af[mf][0], af[mf][1], af[mf][2], af[mf][3], b2, b3);
                }
            }
        }
    }
    __syncthreads();

#pragma unroll
    for (int mf = 0; mf < 4; mf++) {
        int row0 = rowBase + wm * 64 + mf * 16 + lq;
#pragma unroll
        for (int nf = 0; nf < 4; nf++) {
            int col = colBase + wn * 32 + nf * 8 + 2 * lr;
#pragma unroll
            for (int hh = 0; hh < 2; hh++) {
                int row = row0 + hh * 8;
                size_t idx = (size_t)row * N + col;
                float v0 = acc[mf][nf][hh * 2];
                float v1 = acc[mf][nf][hh * 2 + 1];
                if (mode == 3) {
                    float2 a2 = *(const float2*)((const float*)aux + idx);
                    *(float2*)((float*)O + idx) = make_float2(v0 + a2.x, v1 + a2.y);
                } else {
                    if (mode == 1) {
                        v0 = v0 / (1.f + __expf(-v0));
                        v1 = v1 / (1.f + __expf(-v1));
                    } else if (mode == 2) {
                        __half2 g2 = *(const __half2*)((const __half*)aux + idx);
                        v0 *= __low2float(g2);
                        v1 *= __high2float(g2);
                    }
                    *(__half2*)((__half*)O + idx) = __floats2half2_rn(v0, v1);
                }
            }
        }
    }
}

// ---------------- Flash attention, FP16 mma (causal, GQA), cp.async K/V ----
#define VST 72
#define FLASH_SMEM (6 * 64 * VST * 2)   // Qh + 2*Kh + 2*Vh + Ph = 55296 B

__global__ void __launch_bounds__(128) flash_f16_kernel(
    const __half* __restrict__ q, const __half* __restrict__ k,
    const __half* __restrict__ v, __half* __restrict__ o) {
    extern __shared__ __half smh[];
    __half* Qh = smh;                   // [64][VST]
    __half* Kh = smh + 64 * VST;        // 2 bufs
    __half* Vh = smh + 3 * 64 * VST;    // 2 bufs
    __half* Ph = smh + 5 * 64 * VST;
    uint32_t qhBase = (uint32_t)__cvta_generic_to_shared(Qh);
    uint32_t kBase  = (uint32_t)__cvta_generic_to_shared(Kh);
    uint32_t vBase  = (uint32_t)__cvta_generic_to_shared(Vh);
    uint32_t phBase = (uint32_t)__cvta_generic_to_shared(Ph);

    const int qb  = (gridDim.x - 1) - blockIdx.x;   // heavy blocks first
    const int bh  = blockIdx.y;
    const int b   = bh / NH;
    const int h   = bh % NH;
    const int kvh = h / (NH / NKV);
    const int tid  = threadIdx.x;
    const int lane = tid & 31;
    const int warp = tid >> 5;
    const int lq = lane >> 2;
    const int lr = lane & 3;

    // load Q tile [64 x 64] (raw half copy)
    for (int t = tid; t < 64 * 8; t += 128) {
        int r = t >> 3, c8 = (t & 7) * 8;
        uint4 raw = *(const uint4*)(q + ((size_t)((b * S_LEN + qb * 64 + r) * NH + h)) * HDIM + c8);
        *(uint4*)(Qh + r * VST + c8) = raw;
    }

    auto stageKV = [&](int buf, int kb) {
        for (int t = tid; t < 64 * 8; t += 128) {
            int r = t >> 3, c8 = (t & 7) * 8;
            size_t goff = ((size_t)((b * S_LEN + kb * 64 + r) * NKV + kvh)) * HDIM + c8;
            uint32_t soff = (uint32_t)(buf * 64 * VST + r * VST + c8) * 2;
            cpa16(kBase + soff, k + goff);
            cpa16(vBase + soff, v + goff);
        }
    };
    stageKV(0, 0); cpcommit();

    const int wrow = warp * 16;
    const int r0l = wrow + lq;
    const int qrow0 = qb * 64 + r0l;
    const int qrow1 = qrow0 + 8;

    // ldmatrix address selectors
    const int aRowSel = lane & 15;
    const int aKSel   = (lane >> 4) << 3;
    const int bRowSel = (lane & 7) + ((lane >> 4) << 3);
    const int bKSel   = ((lane >> 3) & 1) << 3;

    float m0 = -1e30f, m1 = -1e30f, l0 = 0.f, l1 = 0.f;
    float oacc[8][4];
#pragma unroll
    for (int nf = 0; nf < 8; nf++)
#pragma unroll
        for (int t = 0; t < 4; t++) oacc[nf][t] = 0.f;

    for (int kb = 0; kb <= qb; kb++) {
        const int buf = kb & 1;
        cpwait0();
        __syncthreads();
        if (kb + 1 <= qb) { stageKV(buf ^ 1, kb + 1); cpcommit(); }

        const uint32_t kTile = kBase + (uint32_t)(buf * 64 * VST) * 2;

        // ---- S = Q K^T (ldmatrix fragments) ----
        float sacc[8][4];
#pragma unroll
        for (int nf = 0; nf < 8; nf++)
#pragma unroll
            for (int t = 0; t < 4; t++) sacc[nf][t] = 0.f;

#pragma unroll
        for (int kf = 0; kf < 4; kf++) {
            const int k0 = kf * 16;
            uint32_t a0, a1, a2, a3;
            ldsm_x4(a0, a1, a2, a3,
                    qhBase + (uint32_t)((wrow + aRowSel) * VST + k0 + aKSel) * 2);
#pragma unroll
            for (int ng = 0; ng < 4; ng++) {
                int c0 = ng * 16;
                uint32_t b0, b1, b2, b3;
                ldsm_x4(b0, b1, b2, b3,
                        kTile + (uint32_t)((c0 + bRowSel) * VST + k0 + bKSel) * 2);
                mma_f16(sacc[2 * ng],     a0, a1, a2, a3, b0, b1);
                mma_f16(sacc[2 * ng + 1], a0, a1, a2, a3, b2, b3);
            }
        }

        // ---- scale, mask, online softmax ----
        const bool diag = (kb == qb);
        float rmax0 = -1e30f, rmax1 = -1e30f;
#pragma unroll
        for (int nf = 0; nf < 8; nf++) {
            int jc = kb * 64 + nf * 8 + 2 * lr;
            float s0 = sacc[nf][0] * 0.125f;
            float s1 = sacc[nf][1] * 0.125f;
            float s2 = sacc[nf][2] * 0.125f;
            float s3 = sacc[nf][3] * 0.125f;
            if (diag) {
                if (jc     > qrow0) s0 = -1e30f;
                if (jc + 1 > qrow0) s1 = -1e30f;
                if (jc     > qrow1) s2 = -1e30f;
                if (jc + 1 > qrow1) s3 = -1e30f;
            }
            sacc[nf][0] = s0; sacc[nf][1] = s1; sacc[nf][2] = s2; sacc[nf][3] = s3;
            rmax0 = fmaxf(rmax0, fmaxf(s0, s1));
            rmax1 = fmaxf(rmax1, fmaxf(s2, s3));
        }
        rmax0 = fmaxf(rmax0, __shfl_xor_sync(0xffffffffu, rmax0, 1));
        rmax0 = fmaxf(rmax0, __shfl_xor_sync(0xffffffffu, rmax0, 2));
        rmax1 = fmaxf(rmax1, __shfl_xor_sync(0xffffffffu, rmax1, 1));
        rmax1 = fmaxf(rmax1, __shfl_xor_sync(0xffffffffu, rmax1, 2));

        float mn0 = fmaxf(m0, rmax0);
        float mn1 = fmaxf(m1, rmax1);
        float alpha0 = __expf(m0 - mn0);
        float alpha1 = __expf(m1 - mn1);
        m0 = mn0; m1 = mn1;

        float rsum0 = 0.f, rsum1 = 0.f;
#pragma unroll
        for (int nf = 0; nf < 8; nf++) {
            float p0 = __expf(sacc[nf][0] - mn0);
            float p1 = __expf(sacc[nf][1] - mn0);
            float p2 = __expf(sacc[nf][2] - mn1);
            float p3 = __expf(sacc[nf][3] - mn1);
            sacc[nf][0] = p0; sacc[nf][1] = p1; sacc[nf][2] = p2; sacc[nf][3] = p3;
            rsum0 += p0 + p1;
            rsum1 += p2 + p3;
        }
        rsum0 += __shfl_xor_sync(0xffffffffu, rsum0, 1);
        rsum0 += __shfl_xor_sync(0xffffffffu, rsum0, 2);
        rsum1 += __shfl_xor_sync(0xffffffffu, rsum1, 1);
        rsum1 += __shfl_xor_sync(0xffffffffu, rsum1, 2);
        l0 = l0 * alpha0 + rsum0;
        l1 = l1 * alpha1 + rsum1;

#pragma unroll
        for (int nf = 0; nf < 8; nf++) {
            oacc[nf][0] *= alpha0; oacc[nf][1] *= alpha0;
            oacc[nf][2] *= alpha1; oacc[nf][3] *= alpha1;
        }

        // ---- stage P (half) to smem ----
#pragma unroll
        for (int nf = 0; nf < 8; nf++) {
            int pc = nf * 8 + 2 * lr;
            *(__half2*)(Ph + r0l * VST + pc)       = __floats2half2_rn(sacc[nf][0], sacc[nf][1]);
            *(__half2*)(Ph + (r0l + 8) * VST + pc) = __floats2half2_rn(sacc[nf][2], sacc[nf][3]);
        }
        __syncwarp();

        // ---- O += P V  (P via ldmatrix, V^T via ldmatrix.trans) ----
        const uint32_t vTile = vBase + (uint32_t)(buf * 64 * VST) * 2;
#pragma unroll
        for (int kf = 0; kf < 4; kf++) {
            const int k0 = kf * 16;
            uint32_t a0, a1, a2, a3;
            ldsm_x4(a0, a1, a2, a3,
                    phBase + (uint32_t)((wrow + aRowSel) * VST + k0 + aKSel) * 2);
#pragma unroll
            for (int np = 0; np < 4; np++) {
                const int d0 = np * 16;
                uint32_t addr = vTile +
                    (uint32_t)((k0 + (lane & 15)) * VST + d0 + ((lane & 16) >> 1)) * 2;
                uint32_t bb0, bb1, bb2, bb3;
                asm volatile(
                    "ldmatrix.sync.aligned.m8n8.x4.trans.shared.b16 {%0,%1,%2,%3}, [%4];"
                    : "=r"(bb0), "=r"(bb1), "=r"(bb2), "=r"(bb3) : "r"(addr));
                mma_f16(oacc[2 * np],     a0, a1, a2, a3, bb0, bb1);
                mma_f16(oacc[2 * np + 1], a0, a1, a2, a3, bb2, bb3);
            }
        }
    }

    // ---- epilogue: fp16 out ----
    float inv0 = 1.f / l0;
    float inv1 = 1.f / l1;
    int grow0 = b * S_LEN + qrow0;
    int grow1 = b * S_LEN + qrow1;
#pragma unroll
    for (int nf = 0; nf < 8; nf++) {
        int col = nf * 8 + 2 * lr;
        *(__half2*)(o + ((size_t)(grow0 * NH + h)) * HDIM + col) =
            __floats2half2_rn(oacc[nf][0] * inv0, oacc[nf][1] * inv0);
        *(__half2*)(o + ((size_t)(grow1 * NH + h)) * HDIM + col) =
            __floats2half2_rn(oacc[nf][2] * inv1, oacc[nf][3] * inv1);
    }
}

// ---------------- launch ----------------
extern "C" void kernel_launch(void* const* d_in, const int* in_sizes, int n_in,
                              void* d_out, int out_size) {
    const float* x  = (const float*)d_in[0];
    const float* Wq = (const float*)d_in[1];
    const float* Wk = (const float*)d_in[2];
    const float* Wv = (const float*)d_in[3];
    const float* Wo = (const float*)d_in[4];
    const float* an = (const float*)d_in[5];
    const float* w0 = (const float*)d_in[6];
    const float* w1 = (const float*)d_in[7];
    const float* w2 = (const float*)d_in[8];
    const float* sn = (const float*)d_in[9];
    const float* on = (const float*)d_in[10];
    float* out = (float*)d_out;

    __half *h, *q, *k, *v, *att, *gate;
    __half *hWq, *hWk, *hWv, *hWo, *hw0, *hw1, *hw2;
    float *x1, *x2, *cosT, *sinT;
    cudaGetSymbolAddress((void**)&h,    g_h);
    cudaGetSymbolAddress((void**)&q,    g_q);
    cudaGetSymbolAddress((void**)&k,    g_k);
    cudaGetSymbolAddress((void**)&v,    g_v);
    cudaGetSymbolAddress((void**)&att,  g_att);
    cudaGetSymbolAddress((void**)&gate, g_gate);
    cudaGetSymbolAddress((void**)&x1,   g_x1);
    cudaGetSymbolAddress((void**)&x2,   g_x2);
    cudaGetSymbolAddress((void**)&cosT, g_cosT);
    cudaGetSymbolAddress((void**)&sinT, g_sinT);
    cudaGetSymbolAddress((void**)&hWq,  g_hWq);
    cudaGetSymbolAddress((void**)&hWk,  g_hWk);
    cudaGetSymbolAddress((void**)&hWv,  g_hWv);
    cudaGetSymbolAddress((void**)&hWo,  g_hWo);
    cudaGetSymbolAddress((void**)&hw0,  g_hw0);
    cudaGetSymbolAddress((void**)&hw1,  g_hw1);
    cudaGetSymbolAddress((void**)&hw2,  g_hw2);

    cudaFuncSetAttribute(flash_f16_kernel,
                         cudaFuncAttributeMaxDynamicSharedMemorySize, FLASH_SMEM);
    cudaFuncSetAttribute(gemm_f16_kernel,
                         cudaFuncAttributeMaxDynamicSharedMemorySize, GEMM_SMEM);

    rope_table_kernel<<<(S_LEN * 32 + 255) / 256, 256>>>(cosT, sinT);

    const dim3 tb(32, 8);
    w_t_h_kernel<<<dim3(DMODEL / 32, DMODEL / 32, NLAYER), tb>>>(Wq, hWq, DMODEL, DMODEL);
    w_t_h_kernel<<<dim3(KVD / 32,    DMODEL / 32, NLAYER), tb>>>(Wk, hWk, DMODEL, KVD);
    w_t_h_kernel<<<dim3(KVD / 32,    DMODEL / 32, NLAYER), tb>>>(Wv, hWv, DMODEL, KVD);
    w_t_h_kernel<<<dim3(DMODEL / 32, DMODEL / 32, NLAYER), tb>>>(Wo, hWo, DMODEL, DMODEL);
    w_t_h_kernel<<<dim3(FFDIM / 32,  DMODEL / 32, NLAYER), tb>>>(w0, hw0, DMODEL, FFDIM);
    w_t_h_kernel<<<dim3(FFDIM / 32,  DMODEL / 32, NLAYER), tb>>>(w1, hw1, DMODEL, FFDIM);
    w_t_h_kernel<<<dim3(DMODEL / 32, FFDIM / 32,  NLAYER), tb>>>(w2, hw2, FFDIM, DMODEL);

    const dim3 gN768(DMODEL / 128, M_TOK / 128, 1);
    const dim3 gKV  (KVD / 128,    M_TOK / 128, 2);
    const dim3 gFF  (FFDIM / 128,  M_TOK / 128, 1);

    const float* xin = x;
    for (int l = 0; l < NLAYER; l++) {
        __half* hWq_l = hWq + (size_t)l * DMODEL * DMODEL;
        __half* hWk_l = hWk + (size_t)l * KVD * DMODEL;
        __half* hWv_l = hWv + (size_t)l * KVD * DMODEL;
        __half* hWo_l = hWo + (size_t)l * DMODEL * DMODEL;
        __half* hw0_l = hw0 + (size_t)l * FFDIM * DMODEL;
        __half* hw1_l = hw1 + (size_t)l * FFDIM * DMODEL;
        __half* hw2_l = hw2 + (size_t)l * DMODEL * FFDIM;

        rmsnorm_kernel<<<M_TOK, 256>>>(xin, an + l * DMODEL, h, nullptr);
        gemm_f16_kernel<<<gN768, 256, GEMM_SMEM>>>(h, hWq_l, hWq_l, nullptr, q, q, DMODEL, DMODEL, 0);
        gemm_f16_kernel<<<gKV,   256, GEMM_SMEM>>>(h, hWk_l, hWv_l, nullptr, k, v, KVD, DMODEL, 0);
        rope_kernel<<<M_TOK, 256>>>(q, k, cosT, sinT);
        flash_f16_kernel<<<dim3(S_LEN / 64, BATCH * NH), 128, FLASH_SMEM>>>(q, k, v, att);
        gemm_f16_kernel<<<gN768, 256, GEMM_SMEM>>>(att, hWo_l, hWo_l, xin, x1, x1, DMODEL, DMODEL, 3);
        rmsnorm_kernel<<<M_TOK, 256>>>(x1, sn + l * DMODEL, h, nullptr);
        gemm_f16_kernel<<<gFF, 256, GEMM_SMEM>>>(h, hw0_l, hw0_l, nullptr, gate, gate, FFDIM, DMODEL, 1);
        gemm_f16_kernel<<<gFF, 256, GEMM_SMEM>>>(h, hw1_l, hw1_l, gate, gate, gate, FFDIM, DMODEL, 2);
        gemm_f16_kernel<<<gN768, 256, GEMM_SMEM>>>(gate, hw2_l, hw2_l, x1, x2, x2, DMODEL, FFDIM, 3);
        xin = x2;
    }
    rmsnorm_kernel<<<M_TOK, 256>>>(x2, on, nullptr, out);
}

// round 10
// speedup vs baseline: 2.5470x; 1.0084x over previous
#include <cuda_runtime.h>
#include <cuda_fp16.h>
#include <math.h>
#include <stdint.h>

// ---------------- problem constants ----------------
#define S_LEN  2048
#define BATCH  2
#define DMODEL 768
#define NH     12
#define NKV    4
#define HDIM   64
#define FFDIM  3072
#define NLAYER 2
#define M_TOK  (BATCH * S_LEN)   // 4096 tokens
#define KVD    (NKV * HDIM)      // 256

// ---------------- scratch (device globals; no allocation allowed) ----------
__device__ __align__(16) __half g_h   [M_TOK * DMODEL];
__device__ __align__(16) __half g_q   [M_TOK * DMODEL];
__device__ __align__(16) __half g_k   [M_TOK * KVD];
__device__ __align__(16) __half g_v   [M_TOK * KVD];
__device__ __align__(16) __half g_att [M_TOK * DMODEL];
__device__ __align__(16) __half g_gate[M_TOK * FFDIM];
__device__ __align__(16) float  g_x1  [M_TOK * DMODEL];
__device__ __align__(16) float  g_x2  [M_TOK * DMODEL];
__device__ __align__(16) float  g_cosT[S_LEN * 32];
__device__ __align__(16) float  g_sinT[S_LEN * 32];
// fp16 transposed weights [N][K] per layer
__device__ __align__(16) __half g_hWq[NLAYER * DMODEL * DMODEL];
__device__ __align__(16) __half g_hWk[NLAYER * KVD * DMODEL];
__device__ __align__(16) __half g_hWv[NLAYER * KVD * DMODEL];
__device__ __align__(16) __half g_hWo[NLAYER * DMODEL * DMODEL];
__device__ __align__(16) __half g_hw0[NLAYER * FFDIM * DMODEL];
__device__ __align__(16) __half g_hw1[NLAYER * FFDIM * DMODEL];
__device__ __align__(16) __half g_hw2[NLAYER * DMODEL * FFDIM];

// ---------------- helpers ----------------
__device__ __forceinline__ void mma_f16(float (&c)[4],
                                        uint32_t a0, uint32_t a1, uint32_t a2, uint32_t a3,
                                        uint32_t b0, uint32_t b1) {
    asm volatile(
        "mma.sync.aligned.m16n8k16.row.col.f32.f16.f16.f32 "
        "{%0,%1,%2,%3}, {%4,%5,%6,%7}, {%8,%9}, {%0,%1,%2,%3};"
        : "+f"(c[0]), "+f"(c[1]), "+f"(c[2]), "+f"(c[3])
        : "r"(a0), "r"(a1), "r"(a2), "r"(a3), "r"(b0), "r"(b1));
}
__device__ __forceinline__ void ldsm_x4(uint32_t& r0, uint32_t& r1,
                                        uint32_t& r2, uint32_t& r3, uint32_t addr) {
    asm volatile("ldmatrix.sync.aligned.m8n8.x4.shared.b16 {%0,%1,%2,%3}, [%4];"
                 : "=r"(r0), "=r"(r1), "=r"(r2), "=r"(r3) : "r"(addr));
}
__device__ __forceinline__ void cpa16(uint32_t d, const void* s) {
    asm volatile("cp.async.cg.shared.global [%0], [%1], 16;" :: "r"(d), "l"(s));
}
__device__ __forceinline__ void cpcommit() { asm volatile("cp.async.commit_group;"); }
__device__ __forceinline__ void cpwait1()  { asm volatile("cp.async.wait_group 1;"); }
__device__ __forceinline__ void cpwait0()  { asm volatile("cp.async.wait_group 0;"); }

// ---------------- RoPE tables ----------------
__global__ void rope_table_kernel(float* __restrict__ cosT, float* __restrict__ sinT) {
    int idx = blockIdx.x * blockDim.x + threadIdx.x;
    if (idx >= S_LEN * 32) return;
    int p = idx >> 5, i = idx & 31;
    double f  = exp(-((double)(2 * i) / 64.0) * log(10000.0));
    float ang = (float)p * (float)f;
    cosT[idx] = (float)cos((double)ang);
    sinT[idx] = (float)sin((double)ang);
}

// ---------------- weight transpose + fp16 convert: src[K][N] -> dst[N][K] --
__global__ void w_t_h_kernel(const float* __restrict__ src, __half* __restrict__ dst,
                             int K, int N) {
    __shared__ float tile[32][33];
    int l = blockIdx.z;
    src += (size_t)l * K * N;
    dst += (size_t)l * K * N;
    int nb = blockIdx.x * 32, kb = blockIdx.y * 32;
    int tx = threadIdx.x, ty = threadIdx.y;   // 32 x 8
#pragma unroll
    for (int i = 0; i < 4; i++)
        tile[ty + 8 * i][tx] = src[(size_t)(kb + ty + 8 * i) * N + nb + tx];
    __syncthreads();
#pragma unroll
    for (int i = 0; i < 4; i++)
        dst[(size_t)(nb + ty + 8 * i) * K + kb + tx] = __float2half_rn(tile[tx][ty + 8 * i]);
}

// ---------------- RMSNorm ----------------
__global__ void rmsnorm_kernel(const float* __restrict__ x,
                               const float* __restrict__ w,
                               __half* __restrict__ oh,
                               float* __restrict__ of) {
    int row = blockIdx.x;
    const float* xr = x + (size_t)row * DMODEL;
    float v[3];
    float s = 0.f;
#pragma unroll
    for (int t = 0; t < 3; t++) {
        v[t] = xr[threadIdx.x + t * 256];
        s += v[t] * v[t];
    }
#pragma unroll
    for (int off = 16; off > 0; off >>= 1) s += __shfl_xor_sync(0xffffffffu, s, off);
    __shared__ float red[8];
    if ((threadIdx.x & 31) == 0) red[threadIdx.x >> 5] = s;
    __syncthreads();
    float tot = 0.f;
#pragma unroll
    for (int i = 0; i < 8; i++) tot += red[i];
    float scale = rsqrtf(tot * (1.0f / (float)DMODEL) + 1e-6f);
    if (oh) {
        __half* orow = oh + (size_t)row * DMODEL;
#pragma unroll
        for (int t = 0; t < 3; t++) {
            int c = threadIdx.x + t * 256;
            orow[c] = __float2half_rn(v[t] * scale * w[c]);
        }
    } else {
        float* orow = of + (size_t)row * DMODEL;
#pragma unroll
        for (int t = 0; t < 3; t++) {
            int c = threadIdx.x + t * 256;
            orow[c] = v[t] * scale * w[c];
        }
    }
}

// ---------------- shared GEMM mainloop pieces ----------------
#define KT   32
#define STG  3
#define AST  40
#define BST  40
#define GEMM_SMEM ((STG * 128 * AST + STG * 128 * BST) * 2)   // 61440 bytes

// ---------------- fused QKV GEMM (+RoPE epilogue for Q,K) ------------------
// grid.x: 0..5 -> Q tiles, 6..7 -> K tiles, 8..9 -> V tiles; grid.y = M/128.
__global__ void __launch_bounds__(256, 2) qkv_gemm_kernel(
    const __half* __restrict__ A,
    const __half* __restrict__ Bq, const __half* __restrict__ Bk,
    const __half* __restrict__ Bv,
    __half* __restrict__ q, __half* __restrict__ k, __half* __restrict__ v,
    const float* __restrict__ cosT, const float* __restrict__ sinT) {
    const int bx = blockIdx.x;
    const __half* Bt;
    __half* O;
    int colB, strideO, doRope;
    if (bx < 6)      { Bt = Bq; O = q; colB = bx * 128;      strideO = DMODEL; doRope = 1; }
    else if (bx < 8) { Bt = Bk; O = k; colB = (bx - 6) * 128; strideO = KVD;   doRope = 1; }
    else             { Bt = Bv; O = v; colB = (bx - 8) * 128; strideO = KVD;   doRope = 0; }

    extern __shared__ __half sm[];
    __half* Asm = sm;
    __half* Bsm = sm + STG * 128 * AST;
    uint32_t aBase = (uint32_t)__cvta_generic_to_shared(Asm);
    uint32_t bBase = (uint32_t)__cvta_generic_to_shared(Bsm);

    const int tid  = threadIdx.x;
    const int lane = tid & 31;
    const int warp = tid >> 5;
    const int wm   = warp & 1;
    const int wn   = warp >> 1;
    const int rowBase = blockIdx.y * 128;
    const int lq = lane >> 2;
    const int lr = lane & 3;
    const int K = DMODEL;

    float acc[4][4][4];
#pragma unroll
    for (int i = 0; i < 4; i++)
#pragma unroll
        for (int j = 0; j < 4; j++)
#pragma unroll
            for (int t = 0; t < 4; t++) acc[i][j][t] = 0.f;

    const int T = K / KT;   // 24

    auto stage = [&](int s, int kt) {
#pragma unroll
        for (int c0 = 0; c0 < 2; c0++) {
            int c = tid + c0 * 256;
            int r = c >> 2, k8 = (c & 3) * 8;
            cpa16(aBase + (uint32_t)(s * 128 * AST + r * AST + k8) * 2,
                  A  + (size_t)(rowBase + r) * K + kt * KT + k8);
            cpa16(bBase + (uint32_t)(s * 128 * BST + r * BST + k8) * 2,
                  Bt + (size_t)(colB + r) * K + kt * KT + k8);
        }
    };

    stage(0, 0); cpcommit();
    stage(1, 1); cpcommit();

    const int aRowSel = lane & 15;
    const int aKSel   = (lane >> 4) << 3;
    const int bRowSel = (lane & 7) + ((lane >> 4) << 3);
    const int bKSel   = ((lane >> 3) & 1) << 3;

    for (int t = 0; t < T; t++) {
        cpwait1();
        __syncthreads();
        if (t + 2 < T) stage((t + 2) % STG, t + 2);
        cpcommit();

        const uint32_t aTile = aBase + (uint32_t)((t % STG) * 128 * AST) * 2;
        const uint32_t bTile = bBase + (uint32_t)((t % STG) * 128 * BST) * 2;
#pragma unroll
        for (int kf = 0; kf < 2; kf++) {
            const int k0 = kf * 16;
            uint32_t af[4][4];
#pragma unroll
            for (int mf = 0; mf < 4; mf++) {
                int r0 = wm * 64 + mf * 16;
                ldsm_x4(af[mf][0], af[mf][1], af[mf][2], af[mf][3],
                        aTile + (uint32_t)((r0 + aRowSel) * AST + k0 + aKSel) * 2);
            }
#pragma unroll
            for (int ng = 0; ng < 2; ng++) {
                int c0 = wn * 32 + ng * 16;
                uint32_t b0, b1, b2, b3;
                ldsm_x4(b0, b1, b2, b3,
                        bTile + (uint32_t)((c0 + bRowSel) * BST + k0 + bKSel) * 2);
#pragma unroll
                for (int mf = 0; mf < 4; mf++) {
                    mma_f16(acc[mf][2 * ng],     af[mf][0], af[mf][1], af[mf][2], af[mf][3], b0, b1);
                    mma_f16(acc[mf][2 * ng + 1], af[mf][0], af[mf][1], af[mf][2], af[mf][3], b2, b3);
                }
            }
        }
    }
    __syncthreads();

    // epilogue (fused RoPE for Q/K)
#pragma unroll
    for (int mf = 0; mf < 4; mf++) {
        int row0 = rowBase + wm * 64 + mf * 16 + lq;
#pragma unroll
        for (int nf = 0; nf < 4; nf++) {
            int col = colB + wn * 32 + nf * 8 + 2 * lr;   // even
#pragma unroll
            for (int hh = 0; hh < 2; hh++) {
                int row = row0 + hh * 8;
                float v0 = acc[mf][nf][hh * 2];
                float v1 = acc[mf][nf][hh * 2 + 1];
                if (doRope) {
                    int i = (col & 63) >> 1;
                    int pos = row & (S_LEN - 1);
                    float c = cosT[pos * 32 + i];
                    float s = sinT[pos * 32 + i];
                    float r0 = v0 * c - v1 * s;
                    float r1 = v0 * s + v1 * c;
                    v0 = r0; v1 = r1;
                }
                *(__half2*)(O + (size_t)row * strideO + col) = __floats2half2_rn(v0, v1);
            }
        }
    }
}

// ---------------- generic FP16 GEMM ----------------
// mode: 0 plain(h16), 1 silu(h16), 2 acc*aux16(h16), 3 acc+aux32(f32)
__global__ void __launch_bounds__(256, 2) gemm_f16_kernel(
    const __half* __restrict__ A,
    const __half* __restrict__ B0t, const __half* __restrict__ B1t,
    const void* __restrict__ aux,
    void* __restrict__ O0, void* __restrict__ O1,
    int N, int K, int mode) {
    const __half* Bt = blockIdx.z ? B1t : B0t;
    void*         O  = blockIdx.z ? O1 : O0;
    extern __shared__ __half sm[];
    __half* Asm = sm;
    __half* Bsm = sm + STG * 128 * AST;
    uint32_t aBase = (uint32_t)__cvta_generic_to_shared(Asm);
    uint32_t bBase = (uint32_t)__cvta_generic_to_shared(Bsm);

    const int tid  = threadIdx.x;
    const int lane = tid & 31;
    const int warp = tid >> 5;
    const int wm   = warp & 1;
    const int wn   = warp >> 1;
    const int rowBase = blockIdx.y * 128;
    const int colBase = blockIdx.x * 128;
    const int lq = lane >> 2;
    const int lr = lane & 3;

    float acc[4][4][4];
#pragma unroll
    for (int i = 0; i < 4; i++)
#pragma unroll
        for (int j = 0; j < 4; j++)
#pragma unroll
            for (int t = 0; t < 4; t++) acc[i][j][t] = 0.f;

    const int T = K / KT;

    auto stage = [&](int s, int kt) {
#pragma unroll
        for (int c0 = 0; c0 < 2; c0++) {
            int c = tid + c0 * 256;
            int r = c >> 2, k8 = (c & 3) * 8;
            cpa16(aBase + (uint32_t)(s * 128 * AST + r * AST + k8) * 2,
                  A  + (size_t)(rowBase + r) * K + kt * KT + k8);
            cpa16(bBase + (uint32_t)(s * 128 * BST + r * BST + k8) * 2,
                  Bt + (size_t)(colBase + r) * K + kt * KT + k8);
        }
    };

    stage(0, 0); cpcommit();
    stage(1, 1); cpcommit();

    const int aRowSel = lane & 15;
    const int aKSel   = (lane >> 4) << 3;
    const int bRowSel = (lane & 7) + ((lane >> 4) << 3);
    const int bKSel   = ((lane >> 3) & 1) << 3;

    for (int t = 0; t < T; t++) {
        cpwait1();
        __syncthreads();
        if (t + 2 < T) stage((t + 2) % STG, t + 2);
        cpcommit();

        const uint32_t aTile = aBase + (uint32_t)((t % STG) * 128 * AST) * 2;
        const uint32_t bTile = bBase + (uint32_t)((t % STG) * 128 * BST) * 2;
#pragma unroll
        for (int kf = 0; kf < 2; kf++) {
            const int k0 = kf * 16;
            uint32_t af[4][4];
#pragma unroll
            for (int mf = 0; mf < 4; mf++) {
                int r0 = wm * 64 + mf * 16;
                ldsm_x4(af[mf][0], af[mf][1], af[mf][2], af[mf][3],
                        aTile + (uint32_t)((r0 + aRowSel) * AST + k0 + aKSel) * 2);
            }
#pragma unroll
            for (int ng = 0; ng < 2; ng++) {
                int c0 = wn * 32 + ng * 16;
                uint32_t b0, b1, b2, b3;
                ldsm_x4(b0, b1, b2, b3,
                        bTile + (uint32_t)((c0 + bRowSel) * BST + k0 + bKSel) * 2);
#pragma unroll
                for (int mf = 0; mf < 4; mf++) {
                    mma_f16(acc[mf][2 * ng],     af[mf][0], af[mf][1], af[mf][2], af[mf][3], b0, b1);
                    mma_f16(acc[mf][2 * ng + 1], af[mf][0], af[mf][1], af[mf][2], af[mf][3], b2, b3);
                }
            }
        }
    }
    __syncthreads();

#pragma unroll
    for (int mf = 0; mf < 4; mf++) {
        int row0 = rowBase + wm * 64 + mf * 16 + lq;
#pragma unroll
        for (int nf = 0; nf < 4; nf++) {
            int col = colBase + wn * 32 + nf * 8 + 2 * lr;
#pragma unroll
            for (int hh = 0; hh < 2; hh++) {
                int row = row0 + hh * 8;
                size_t idx = (size_t)row * N + col;
                float v0 = acc[mf][nf][hh * 2];
                float v1 = acc[mf][nf][hh * 2 + 1];
                if (mode == 3) {
                    float2 a2 = *(const float2*)((const float*)aux + idx);
                    *(float2*)((float*)O + idx) = make_float2(v0 + a2.x, v1 + a2.y);
                } else {
                    if (mode == 1) {
                        v0 = v0 / (1.f + __expf(-v0));
                        v1 = v1 / (1.f + __expf(-v1));
                    } else if (mode == 2) {
                        __half2 g2 = *(const __half2*)((const __half*)aux + idx);
                        v0 *= __low2float(g2);
                        v1 *= __high2float(g2);
                    }
                    *(__half2*)((__half*)O + idx) = __floats2half2_rn(v0, v1);
                }
            }
        }
    }
}

// ---------------- Flash attention, FP16 mma (causal, GQA), cp.async K/V ----
#define VST 72
#define FLASH_SMEM (6 * 64 * VST * 2)

__global__ void __launch_bounds__(128) flash_f16_kernel(
    const __half* __restrict__ q, const __half* __restrict__ k,
    const __half* __restrict__ v, __half* __restrict__ o) {
    extern __shared__ __half smh[];
    __half* Qh = smh;
    __half* Kh = smh + 64 * VST;
    __half* Vh = smh + 3 * 64 * VST;
    __half* Ph = smh + 5 * 64 * VST;
    uint32_t qhBase = (uint32_t)__cvta_generic_to_shared(Qh);
    uint32_t kBase  = (uint32_t)__cvta_generic_to_shared(Kh);
    uint32_t vBase  = (uint32_t)__cvta_generic_to_shared(Vh);
    uint32_t phBase = (uint32_t)__cvta_generic_to_shared(Ph);

    const int qb  = (gridDim.x - 1) - blockIdx.x;
    const int bh  = blockIdx.y;
    const int b   = bh / NH;
    const int h   = bh % NH;
    const int kvh = h / (NH / NKV);
    const int tid  = threadIdx.x;
    const int lane = tid & 31;
    const int warp = tid >> 5;
    const int lq = lane >> 2;
    const int lr = lane & 3;

    for (int t = tid; t < 64 * 8; t += 128) {
        int r = t >> 3, c8 = (t & 7) * 8;
        uint4 raw = *(const uint4*)(q + ((size_t)((b * S_LEN + qb * 64 + r) * NH + h)) * HDIM + c8);
        *(uint4*)(Qh + r * VST + c8) = raw;
    }

    auto stageKV = [&](int buf, int kb) {
        for (int t = tid; t < 64 * 8; t += 128) {
            int r = t >> 3, c8 = (t & 7) * 8;
            size_t goff = ((size_t)((b * S_LEN + kb * 64 + r) * NKV + kvh)) * HDIM + c8;
            uint32_t soff = (uint32_t)(buf * 64 * VST + r * VST + c8) * 2;
            cpa16(kBase + soff, k + goff);
            cpa16(vBase + soff, v + goff);
        }
    };
    stageKV(0, 0); cpcommit();

    const int wrow = warp * 16;
    const int r0l = wrow + lq;
    const int qrow0 = qb * 64 + r0l;
    const int qrow1 = qrow0 + 8;

    const int aRowSel = lane & 15;
    const int aKSel   = (lane >> 4) << 3;
    const int bRowSel = (lane & 7) + ((lane >> 4) << 3);
    const int bKSel   = ((lane >> 3) & 1) << 3;

    float m0 = -1e30f, m1 = -1e30f, l0 = 0.f, l1 = 0.f;
    float oacc[8][4];
#pragma unroll
    for (int nf = 0; nf < 8; nf++)
#pragma unroll
        for (int t = 0; t < 4; t++) oacc[nf][t] = 0.f;

    for (int kb = 0; kb <= qb; kb++) {
        const int buf = kb & 1;
        cpwait0();
        __syncthreads();
        if (kb + 1 <= qb) { stageKV(buf ^ 1, kb + 1); cpcommit(); }

        const uint32_t kTile = kBase + (uint32_t)(buf * 64 * VST) * 2;

        float sacc[8][4];
#pragma unroll
        for (int nf = 0; nf < 8; nf++)
#pragma unroll
            for (int t = 0; t < 4; t++) sacc[nf][t] = 0.f;

#pragma unroll
        for (int kf = 0; kf < 4; kf++) {
            const int k0 = kf * 16;
            uint32_t a0, a1, a2, a3;
            ldsm_x4(a0, a1, a2, a3,
                    qhBase + (uint32_t)((wrow + aRowSel) * VST + k0 + aKSel) * 2);
#pragma unroll
            for (int ng = 0; ng < 4; ng++) {
                int c0 = ng * 16;
                uint32_t b0, b1, b2, b3;
                ldsm_x4(b0, b1, b2, b3,
                        kTile + (uint32_t)((c0 + bRowSel) * VST + k0 + bKSel) * 2);
                mma_f16(sacc[2 * ng],     a0, a1, a2, a3, b0, b1);
                mma_f16(sacc[2 * ng + 1], a0, a1, a2, a3, b2, b3);
            }
        }

        const bool diag = (kb == qb);
        float rmax0 = -1e30f, rmax1 = -1e30f;
#pragma unroll
        for (int nf = 0; nf < 8; nf++) {
            int jc = kb * 64 + nf * 8 + 2 * lr;
            float s0 = sacc[nf][0] * 0.125f;
            float s1 = sacc[nf][1] * 0.125f;
            float s2 = sacc[nf][2] * 0.125f;
            float s3 = sacc[nf][3] * 0.125f;
            if (diag) {
                if (jc     > qrow0) s0 = -1e30f;
                if (jc + 1 > qrow0) s1 = -1e30f;
                if (jc     > qrow1) s2 = -1e30f;
                if (jc + 1 > qrow1) s3 = -1e30f;
            }
            sacc[nf][0] = s0; sacc[nf][1] = s1; sacc[nf][2] = s2; sacc[nf][3] = s3;
            rmax0 = fmaxf(rmax0, fmaxf(s0, s1));
            rmax1 = fmaxf(rmax1, fmaxf(s2, s3));
        }
        rmax0 = fmaxf(rmax0, __shfl_xor_sync(0xffffffffu, rmax0, 1));
        rmax0 = fmaxf(rmax0, __shfl_xor_sync(0xffffffffu, rmax0, 2));
        rmax1 = fmaxf(rmax1, __shfl_xor_sync(0xffffffffu, rmax1, 1));
        rmax1 = fmaxf(rmax1, __shfl_xor_sync(0xffffffffu, rmax1, 2));

        float mn0 = fmaxf(m0, rmax0);
        float mn1 = fmaxf(m1, rmax1);
        float alpha0 = __expf(m0 - mn0);
        float alpha1 = __expf(m1 - mn1);
        m0 = mn0; m1 = mn1;

        float rsum0 = 0.f, rsum1 = 0.f;
#pragma unroll
        for (int nf = 0; nf < 8; nf++) {
            float p0 = __expf(sacc[nf][0] - mn0);
            float p1 = __expf(sacc[nf][1] - mn0);
            float p2 = __expf(sacc[nf][2] - mn1);
            float p3 = __expf(sacc[nf][3] - mn1);
            sacc[nf][0] = p0; sacc[nf][1] = p1; sacc[nf][2] = p2; sacc[nf][3] = p3;
            rsum0 += p0 + p1;
            rsum1 += p2 + p3;
        }
        rsum0 += __shfl_xor_sync(0xffffffffu, rsum0, 1);
        rsum0 += __shfl_xor_sync(0xffffffffu, rsum0, 2);
        rsum1 += __shfl_xor_sync(0xffffffffu, rsum1, 1);
        rsum1 += __shfl_xor_sync(0xffffffffu, rsum1, 2);
        l0 = l0 * alpha0 + rsum0;
        l1 = l1 * alpha1 + rsum1;

#pragma unroll
        for (int nf = 0; nf < 8; nf++) {
            oacc[nf][0] *= alpha0; oacc[nf][1] *= alpha0;
            oacc[nf][2] *= alpha1; oacc[nf][3] *= alpha1;
        }

#pragma unroll
        for (int nf = 0; nf < 8; nf++) {
            int pc = nf * 8 + 2 * lr;
            *(__half2*)(Ph + r0l * VST + pc)       = __floats2half2_rn(sacc[nf][0], sacc[nf][1]);
            *(__half2*)(Ph + (r0l + 8) * VST + pc) = __floats2half2_rn(sacc[nf][2], sacc[nf][3]);
        }
        __syncwarp();

        const uint32_t vTile = vBase + (uint32_t)(buf * 64 * VST) * 2;
#pragma unroll
        for (int kf = 0; kf < 4; kf++) {
            const int k0 = kf * 16;
            uint32_t a0, a1, a2, a3;
            ldsm_x4(a0, a1, a2, a3,
                    phBase + (uint32_t)((wrow + aRowSel) * VST + k0 + aKSel) * 2);
#pragma unroll
            for (int np = 0; np < 4; np++) {
                const int d0 = np * 16;
                uint32_t addr = vTile +
                    (uint32_t)((k0 + (lane & 15)) * VST + d0 + ((lane & 16) >> 1)) * 2;
                uint32_t bb0, bb1, bb2, bb3;
                asm volatile(
                    "ldmatrix.sync.aligned.m8n8.x4.trans.shared.b16 {%0,%1,%2,%3}, [%4];"
                    : "=r"(bb0), "=r"(bb1), "=r"(bb2), "=r"(bb3) : "r"(addr));
                mma_f16(oacc[2 * np],     a0, a1, a2, a3, bb0, bb1);
                mma_f16(oacc[2 * np + 1], a0, a1, a2, a3, bb2, bb3);
            }
        }
    }

    float inv0 = 1.f / l0;
    float inv1 = 1.f / l1;
    int grow0 = b * S_LEN + qrow0;
    int grow1 = b * S_LEN + qrow1;
#pragma unroll
    for (int nf = 0; nf < 8; nf++) {
        int col = nf * 8 + 2 * lr;
        *(__half2*)(o + ((size_t)(grow0 * NH + h)) * HDIM + col) =
            __floats2half2_rn(oacc[nf][0] * inv0, oacc[nf][1] * inv0);
        *(__half2*)(o + ((size_t)(grow1 * NH + h)) * HDIM + col) =
            __floats2half2_rn(oacc[nf][2] * inv1, oacc[nf][3] * inv1);
    }
}

// ---------------- launch ----------------
extern "C" void kernel_launch(void* const* d_in, const int* in_sizes, int n_in,
                              void* d_out, int out_size) {
    const float* x  = (const float*)d_in[0];
    const float* Wq = (const float*)d_in[1];
    const float* Wk = (const float*)d_in[2];
    const float* Wv = (const float*)d_in[3];
    const float* Wo = (const float*)d_in[4];
    const float* an = (const float*)d_in[5];
    const float* w0 = (const float*)d_in[6];
    const float* w1 = (const float*)d_in[7];
    const float* w2 = (const float*)d_in[8];
    const float* sn = (const float*)d_in[9];
    const float* on = (const float*)d_in[10];
    float* out = (float*)d_out;

    __half *h, *q, *k, *v, *att, *gate;
    __half *hWq, *hWk, *hWv, *hWo, *hw0, *hw1, *hw2;
    float *x1, *x2, *cosT, *sinT;
    cudaGetSymbolAddress((void**)&h,    g_h);
    cudaGetSymbolAddress((void**)&q,    g_q);
    cudaGetSymbolAddress((void**)&k,    g_k);
    cudaGetSymbolAddress((void**)&v,    g_v);
    cudaGetSymbolAddress((void**)&att,  g_att);
    cudaGetSymbolAddress((void**)&gate, g_gate);
    cudaGetSymbolAddress((void**)&x1,   g_x1);
    cudaGetSymbolAddress((void**)&x2,   g_x2);
    cudaGetSymbolAddress((void**)&cosT, g_cosT);
    cudaGetSymbolAddress((void**)&sinT, g_sinT);
    cudaGetSymbolAddress((void**)&hWq,  g_hWq);
    cudaGetSymbolAddress((void**)&hWk,  g_hWk);
    cudaGetSymbolAddress((void**)&hWv,  g_hWv);
    cudaGetSymbolAddress((void**)&hWo,  g_hWo);
    cudaGetSymbolAddress((void**)&hw0,  g_hw0);
    cudaGetSymbolAddress((void**)&hw1,  g_hw1);
    cudaGetSymbolAddress((void**)&hw2,  g_hw2);

    cudaFuncSetAttribute(flash_f16_kernel,
                         cudaFuncAttributeMaxDynamicSharedMemorySize, FLASH_SMEM);
    cudaFuncSetAttribute(gemm_f16_kernel,
                         cudaFuncAttributeMaxDynamicSharedMemorySize, GEMM_SMEM);
    cudaFuncSetAttribute(qkv_gemm_kernel,
                         cudaFuncAttributeMaxDynamicSharedMemorySize, GEMM_SMEM);

    const dim3 tb(32, 8);
    const dim3 gQKV (10, M_TOK / 128, 1);
    const dim3 gN768(DMODEL / 128, M_TOK / 128, 1);
    const dim3 gFF  (FFDIM / 128,  M_TOK / 128, 1);

    // launch order: indices 0..5 arranged so ncu (-s 5 -c 1) captures qkv_gemm
    rope_table_kernel<<<(S_LEN * 32 + 255) / 256, 256>>>(cosT, sinT);            // 0
    w_t_h_kernel<<<dim3(DMODEL / 32, DMODEL / 32, NLAYER), tb>>>(Wq, hWq, DMODEL, DMODEL); // 1
    w_t_h_kernel<<<dim3(KVD / 32,    DMODEL / 32, NLAYER), tb>>>(Wk, hWk, DMODEL, KVD);    // 2
    w_t_h_kernel<<<dim3(KVD / 32,    DMODEL / 32, NLAYER), tb>>>(Wv, hWv, DMODEL, KVD);    // 3
    rmsnorm_kernel<<<M_TOK, 256>>>(x, an, h, nullptr);                           // 4
    qkv_gemm_kernel<<<gQKV, 256, GEMM_SMEM>>>(h, hWq, hWk, hWv, q, k, v, cosT, sinT); // 5 <- profiled
    // remaining weight transposes (needed before Wo/w0/w1/w2 GEMMs)
    w_t_h_kernel<<<dim3(DMODEL / 32, DMODEL / 32, NLAYER), tb>>>(Wo, hWo, DMODEL, DMODEL);
    w_t_h_kernel<<<dim3(FFDIM / 32,  DMODEL / 32, NLAYER), tb>>>(w0, hw0, DMODEL, FFDIM);
    w_t_h_kernel<<<dim3(FFDIM / 32,  DMODEL / 32, NLAYER), tb>>>(w1, hw1, DMODEL, FFDIM);
    w_t_h_kernel<<<dim3(DMODEL / 32, FFDIM / 32,  NLAYER), tb>>>(w2, hw2, FFDIM, DMODEL);

    const float* xin = x;
    for (int l = 0; l < NLAYER; l++) {
        __half* hWq_l = hWq + (size_t)l * DMODEL * DMODEL;
        __half* hWk_l = hWk + (size_t)l * KVD * DMODEL;
        __half* hWv_l = hWv + (size_t)l * KVD * DMODEL;
        __half* hWo_l = hWo + (size_t)l * DMODEL * DMODEL;
        __half* hw0_l = hw0 + (size_t)l * FFDIM * DMODEL;
        __half* hw1_l = hw1 + (size_t)l * FFDIM * DMODEL;
        __half* hw2_l = hw2 + (size_t)l * DMODEL * FFDIM;

        if (l > 0) {
            rmsnorm_kernel<<<M_TOK, 256>>>(xin, an + l * DMODEL, h, nullptr);
            qkv_gemm_kernel<<<gQKV, 256, GEMM_SMEM>>>(h, hWq_l, hWk_l, hWv_l,
                                                      q, k, v, cosT, sinT);
        }
        flash_f16_kernel<<<dim3(S_LEN / 64, BATCH * NH), 128, FLASH_SMEM>>>(q, k, v, att);
        gemm_f16_kernel<<<gN768, 256, GEMM_SMEM>>>(att, hWo_l, hWo_l, xin, x1, x1, DMODEL, DMODEL, 3);
        rmsnorm_kernel<<<M_TOK, 256>>>(x1, sn + l * DMODEL, h, nullptr);
        gemm_f16_kernel<<<gFF, 256, GEMM_SMEM>>>(h, hw0_l, hw0_l, nullptr, gate, gate, FFDIM, DMODEL, 1);
        gemm_f16_kernel<<<gFF, 256, GEMM_SMEM>>>(h, hw1_l, hw1_l, gate, gate, gate, FFDIM, DMODEL, 2);
        gemm_f16_kernel<<<gN768, 256, GEMM_SMEM>>>(gate, hw2_l, hw2_l, x1, x2, x2, DMODEL, FFDIM, 3);
        xin = x2;
    }
    rmsnorm_kernel<<<M_TOK, 256>>>(x2, on, nullptr, out);
}

// round 11
// speedup vs baseline: 2.6315x; 1.0332x over previous
#include <cuda_runtime.h>
#include <cuda_fp16.h>
#include <math.h>
#include <stdint.h>

// ---------------- problem constants ----------------
#define S_LEN  2048
#define BATCH  2
#define DMODEL 768
#define NH     12
#define NKV    4
#define HDIM   64
#define FFDIM  3072
#define NLAYER 2
#define M_TOK  (BATCH * S_LEN)   // 4096 tokens
#define KVD    (NKV * HDIM)      // 256

// ---------------- scratch (device globals; no allocation allowed) ----------
__device__ __align__(16) __half g_h    [M_TOK * DMODEL];
__device__ __align__(16) __half g_q    [M_TOK * DMODEL];
__device__ __align__(16) __half g_k    [M_TOK * KVD];
__device__ __align__(16) __half g_v    [M_TOK * KVD];
__device__ __align__(16) __half g_att  [M_TOK * DMODEL];
__device__ __align__(16) __half g_gate [M_TOK * FFDIM];
__device__ __align__(16) __half g_gate2[M_TOK * FFDIM];
__device__ __align__(16) float  g_x1   [M_TOK * DMODEL];
__device__ __align__(16) float  g_x2   [M_TOK * DMODEL];
__device__ __align__(16) float  g_cosT [S_LEN * 32];
__device__ __align__(16) float  g_sinT [S_LEN * 32];
// fp16 transposed weights [N][K] per layer
__device__ __align__(16) __half g_hWq[NLAYER * DMODEL * DMODEL];
__device__ __align__(16) __half g_hWk[NLAYER * KVD * DMODEL];
__device__ __align__(16) __half g_hWv[NLAYER * KVD * DMODEL];
__device__ __align__(16) __half g_hWo[NLAYER * DMODEL * DMODEL];
__device__ __align__(16) __half g_hw0[NLAYER * FFDIM * DMODEL];
__device__ __align__(16) __half g_hw1[NLAYER * FFDIM * DMODEL];
__device__ __align__(16) __half g_hw2[NLAYER * DMODEL * FFDIM];

// ---------------- helpers ----------------
__device__ __forceinline__ void mma_f16(float (&c)[4],
                                        uint32_t a0, uint32_t a1, uint32_t a2, uint32_t a3,
                                        uint32_t b0, uint32_t b1) {
    asm volatile(
        "mma.sync.aligned.m16n8k16.row.col.f32.f16.f16.f32 "
        "{%0,%1,%2,%3}, {%4,%5,%6,%7}, {%8,%9}, {%0,%1,%2,%3};"
        : "+f"(c[0]), "+f"(c[1]), "+f"(c[2]), "+f"(c[3])
        : "r"(a0), "r"(a1), "r"(a2), "r"(a3), "r"(b0), "r"(b1));
}
__device__ __forceinline__ void ldsm_x4(uint32_t& r0, uint32_t& r1,
                                        uint32_t& r2, uint32_t& r3, uint32_t addr) {
    asm volatile("ldmatrix.sync.aligned.m8n8.x4.shared.b16 {%0,%1,%2,%3}, [%4];"
                 : "=r"(r0), "=r"(r1), "=r"(r2), "=r"(r3) : "r"(addr));
}
__device__ __forceinline__ void cpa16(uint32_t d, const void* s) {
    asm volatile("cp.async.cg.shared.global [%0], [%1], 16;" :: "r"(d), "l"(s));
}
__device__ __forceinline__ void cpcommit() { asm volatile("cp.async.commit_group;"); }
__device__ __forceinline__ void cpwait1()  { asm volatile("cp.async.wait_group 1;"); }
__device__ __forceinline__ void cpwait0()  { asm volatile("cp.async.wait_group 0;"); }

// ---------------- RoPE tables ----------------
__global__ void rope_table_kernel(float* __restrict__ cosT, float* __restrict__ sinT) {
    int idx = blockIdx.x * blockDim.x + threadIdx.x;
    if (idx >= S_LEN * 32) return;
    int p = idx >> 5, i = idx & 31;
    double f  = exp(-((double)(2 * i) / 64.0) * log(10000.0));
    float ang = (float)p * (float)f;
    cosT[idx] = (float)cos((double)ang);
    sinT[idx] = (float)sin((double)ang);
}

// ---------------- weight transpose + fp16 convert: src[K][N] -> dst[N][K] --
__global__ void w_t_h_kernel(const float* __restrict__ src, __half* __restrict__ dst,
                             int K, int N) {
    __shared__ float tile[32][33];
    int l = blockIdx.z;
    src += (size_t)l * K * N;
    dst += (size_t)l * K * N;
    int nb = blockIdx.x * 32, kb = blockIdx.y * 32;
    int tx = threadIdx.x, ty = threadIdx.y;   // 32 x 8
#pragma unroll
    for (int i = 0; i < 4; i++)
        tile[ty + 8 * i][tx] = src[(size_t)(kb + ty + 8 * i) * N + nb + tx];
    __syncthreads();
#pragma unroll
    for (int i = 0; i < 4; i++)
        dst[(size_t)(nb + ty + 8 * i) * K + kb + tx] = __float2half_rn(tile[tx][ty + 8 * i]);
}

// ---------------- RMSNorm ----------------
__global__ void rmsnorm_kernel(const float* __restrict__ x,
                               const float* __restrict__ w,
                               __half* __restrict__ oh,
                               float* __restrict__ of) {
    int row = blockIdx.x;
    const float* xr = x + (size_t)row * DMODEL;
    float v[3];
    float s = 0.f;
#pragma unroll
    for (int t = 0; t < 3; t++) {
        v[t] = xr[threadIdx.x + t * 256];
        s += v[t] * v[t];
    }
#pragma unroll
    for (int off = 16; off > 0; off >>= 1) s += __shfl_xor_sync(0xffffffffu, s, off);
    __shared__ float red[8];
    if ((threadIdx.x & 31) == 0) red[threadIdx.x >> 5] = s;
    __syncthreads();
    float tot = 0.f;
#pragma unroll
    for (int i = 0; i < 8; i++) tot += red[i];
    float scale = rsqrtf(tot * (1.0f / (float)DMODEL) + 1e-6f);
    if (oh) {
        __half* orow = oh + (size_t)row * DMODEL;
#pragma unroll
        for (int t = 0; t < 3; t++) {
            int c = threadIdx.x + t * 256;
            orow[c] = __float2half_rn(v[t] * scale * w[c]);
        }
    } else {
        float* orow = of + (size_t)row * DMODEL;
#pragma unroll
        for (int t = 0; t < 3; t++) {
            int c = threadIdx.x + t * 256;
            orow[c] = v[t] * scale * w[c];
        }
    }
}

// ---------------- shared GEMM mainloop constants ----------------
#define KT   32
#define STG  3
#define AST  40
#define BST  40
#define GEMM_SMEM ((STG * 128 * AST + STG * 128 * BST) * 2)   // 61440 bytes
#define GATE_SMEM ((2 * 128 * AST + STG * 128 * BST) * 2)     // 51200 bytes

// ---------------- fused QKV GEMM (+RoPE epilogue for Q,K) ------------------
__global__ void __launch_bounds__(256, 2) qkv_gemm_kernel(
    const __half* __restrict__ A,
    const __half* __restrict__ Bq, const __half* __restrict__ Bk,
    const __half* __restrict__ Bv,
    __half* __restrict__ q, __half* __restrict__ k, __half* __restrict__ v,
    const float* __restrict__ cosT, const float* __restrict__ sinT) {
    const int bx = blockIdx.x;
    const __half* Bt;
    __half* O;
    int colB, strideO, doRope;
    if (bx < 6)      { Bt = Bq; O = q; colB = bx * 128;       strideO = DMODEL; doRope = 1; }
    else if (bx < 8) { Bt = Bk; O = k; colB = (bx - 6) * 128; strideO = KVD;    doRope = 1; }
    else             { Bt = Bv; O = v; colB = (bx - 8) * 128; strideO = KVD;    doRope = 0; }

    extern __shared__ __half sm[];
    __half* Asm = sm;
    __half* Bsm = sm + STG * 128 * AST;
    uint32_t aBase = (uint32_t)__cvta_generic_to_shared(Asm);
    uint32_t bBase = (uint32_t)__cvta_generic_to_shared(Bsm);

    const int tid  = threadIdx.x;
    const int lane = tid & 31;
    const int warp = tid >> 5;
    const int wm   = warp & 1;
    const int wn   = warp >> 1;
    const int rowBase = blockIdx.y * 128;
    const int lq = lane >> 2;
    const int lr = lane & 3;
    const int K = DMODEL;

    float acc[4][4][4];
#pragma unroll
    for (int i = 0; i < 4; i++)
#pragma unroll
        for (int j = 0; j < 4; j++)
#pragma unroll
            for (int t = 0; t < 4; t++) acc[i][j][t] = 0.f;

    const int T = K / KT;

    auto stage = [&](int s, int kt) {
#pragma unroll
        for (int c0 = 0; c0 < 2; c0++) {
            int c = tid + c0 * 256;
            int r = c >> 2, k8 = (c & 3) * 8;
            cpa16(aBase + (uint32_t)(s * 128 * AST + r * AST + k8) * 2,
                  A  + (size_t)(rowBase + r) * K + kt * KT + k8);
            cpa16(bBase + (uint32_t)(s * 128 * BST + r * BST + k8) * 2,
                  Bt + (size_t)(colB + r) * K + kt * KT + k8);
        }
    };

    stage(0, 0); cpcommit();
    stage(1, 1); cpcommit();

    const int aRowSel = lane & 15;
    const int aKSel   = (lane >> 4) << 3;
    const int bRowSel = (lane & 7) + ((lane >> 4) << 3);
    const int bKSel   = ((lane >> 3) & 1) << 3;

    for (int t = 0; t < T; t++) {
        cpwait1();
        __syncthreads();
        if (t + 2 < T) stage((t + 2) % STG, t + 2);
        cpcommit();

        const uint32_t aTile = aBase + (uint32_t)((t % STG) * 128 * AST) * 2;
        const uint32_t bTile = bBase + (uint32_t)((t % STG) * 128 * BST) * 2;
#pragma unroll
        for (int kf = 0; kf < 2; kf++) {
            const int k0 = kf * 16;
            uint32_t af[4][4];
#pragma unroll
            for (int mf = 0; mf < 4; mf++) {
                int r0 = wm * 64 + mf * 16;
                ldsm_x4(af[mf][0], af[mf][1], af[mf][2], af[mf][3],
                        aTile + (uint32_t)((r0 + aRowSel) * AST + k0 + aKSel) * 2);
            }
#pragma unroll
            for (int ng = 0; ng < 2; ng++) {
                int c0 = wn * 32 + ng * 16;
                uint32_t b0, b1, b2, b3;
                ldsm_x4(b0, b1, b2, b3,
                        bTile + (uint32_t)((c0 + bRowSel) * BST + k0 + bKSel) * 2);
#pragma unroll
                for (int mf = 0; mf < 4; mf++) {
                    mma_f16(acc[mf][2 * ng],     af[mf][0], af[mf][1], af[mf][2], af[mf][3], b0, b1);
                    mma_f16(acc[mf][2 * ng + 1], af[mf][0], af[mf][1], af[mf][2], af[mf][3], b2, b3);
                }
            }
        }
    }
    __syncthreads();

#pragma unroll
    for (int mf = 0; mf < 4; mf++) {
        int row0 = rowBase + wm * 64 + mf * 16 + lq;
#pragma unroll
        for (int nf = 0; nf < 4; nf++) {
            int col = colB + wn * 32 + nf * 8 + 2 * lr;
#pragma unroll
            for (int hh = 0; hh < 2; hh++) {
                int row = row0 + hh * 8;
                float v0 = acc[mf][nf][hh * 2];
                float v1 = acc[mf][nf][hh * 2 + 1];
                if (doRope) {
                    int i = (col & 63) >> 1;
                    int pos = row & (S_LEN - 1);
                    float c = cosT[pos * 32 + i];
                    float s = sinT[pos * 32 + i];
                    float r0 = v0 * c - v1 * s;
                    float r1 = v0 * s + v1 * c;
                    v0 = r0; v1 = r1;
                }
                *(__half2*)(O + (size_t)row * strideO + col) = __floats2half2_rn(v0, v1);
            }
        }
    }
}

// ---------------- generic FP16 GEMM ----------------
// mode: 0 plain(h16), 1 silu(h16), 3 acc+aux32(f32),
//       5 dual: z==0 -> silu -> O0 ; z==1 -> plain -> O1
__global__ void __launch_bounds__(256, 2) gemm_f16_kernel(
    const __half* __restrict__ A,
    const __half* __restrict__ B0t, const __half* __restrict__ B1t,
    const void* __restrict__ aux,
    void* __restrict__ O0, void* __restrict__ O1,
    int N, int K, int mode) {
    const __half* Bt = blockIdx.z ? B1t : B0t;
    void*         O  = blockIdx.z ? O1 : O0;
    extern __shared__ __half sm[];
    __half* Asm = sm;
    __half* Bsm = sm + STG * 128 * AST;
    uint32_t aBase = (uint32_t)__cvta_generic_to_shared(Asm);
    uint32_t bBase = (uint32_t)__cvta_generic_to_shared(Bsm);

    const int tid  = threadIdx.x;
    const int lane = tid & 31;
    const int warp = tid >> 5;
    const int wm   = warp & 1;
    const int wn   = warp >> 1;
    const int rowBase = blockIdx.y * 128;
    const int colBase = blockIdx.x * 128;
    const int lq = lane >> 2;
    const int lr = lane & 3;
    const int doSilu = (mode == 1) || (mode == 5 && blockIdx.z == 0);

    float acc[4][4][4];
#pragma unroll
    for (int i = 0; i < 4; i++)
#pragma unroll
        for (int j = 0; j < 4; j++)
#pragma unroll
            for (int t = 0; t < 4; t++) acc[i][j][t] = 0.f;

    const int T = K / KT;

    auto stage = [&](int s, int kt) {
#pragma unroll
        for (int c0 = 0; c0 < 2; c0++) {
            int c = tid + c0 * 256;
            int r = c >> 2, k8 = (c & 3) * 8;
            cpa16(aBase + (uint32_t)(s * 128 * AST + r * AST + k8) * 2,
                  A  + (size_t)(rowBase + r) * K + kt * KT + k8);
            cpa16(bBase + (uint32_t)(s * 128 * BST + r * BST + k8) * 2,
                  Bt + (size_t)(colBase + r) * K + kt * KT + k8);
        }
    };

    stage(0, 0); cpcommit();
    stage(1, 1); cpcommit();

    const int aRowSel = lane & 15;
    const int aKSel   = (lane >> 4) << 3;
    const int bRowSel = (lane & 7) + ((lane >> 4) << 3);
    const int bKSel   = ((lane >> 3) & 1) << 3;

    for (int t = 0; t < T; t++) {
        cpwait1();
        __syncthreads();
        if (t + 2 < T) stage((t + 2) % STG, t + 2);
        cpcommit();

        const uint32_t aTile = aBase + (uint32_t)((t % STG) * 128 * AST) * 2;
        const uint32_t bTile = bBase + (uint32_t)((t % STG) * 128 * BST) * 2;
#pragma unroll
        for (int kf = 0; kf < 2; kf++) {
            const int k0 = kf * 16;
            uint32_t af[4][4];
#pragma unroll
            for (int mf = 0; mf < 4; mf++) {
                int r0 = wm * 64 + mf * 16;
                ldsm_x4(af[mf][0], af[mf][1], af[mf][2], af[mf][3],
                        aTile + (uint32_t)((r0 + aRowSel) * AST + k0 + aKSel) * 2);
            }
#pragma unroll
            for (int ng = 0; ng < 2; ng++) {
                int c0 = wn * 32 + ng * 16;
                uint32_t b0, b1, b2, b3;
                ldsm_x4(b0, b1, b2, b3,
                        bTile + (uint32_t)((c0 + bRowSel) * BST + k0 + bKSel) * 2);
#pragma unroll
                for (int mf = 0; mf < 4; mf++) {
                    mma_f16(acc[mf][2 * ng],     af[mf][0], af[mf][1], af[mf][2], af[mf][3], b0, b1);
                    mma_f16(acc[mf][2 * ng + 1], af[mf][0], af[mf][1], af[mf][2], af[mf][3], b2, b3);
                }
            }
        }
    }
    __syncthreads();

#pragma unroll
    for (int mf = 0; mf < 4; mf++) {
        int row0 = rowBase + wm * 64 + mf * 16 + lq;
#pragma unroll
        for (int nf = 0; nf < 4; nf++) {
            int col = colBase + wn * 32 + nf * 8 + 2 * lr;
#pragma unroll
            for (int hh = 0; hh < 2; hh++) {
                int row = row0 + hh * 8;
                size_t idx = (size_t)row * N + col;
                float v0 = acc[mf][nf][hh * 2];
                float v1 = acc[mf][nf][hh * 2 + 1];
                if (mode == 3) {
                    float2 a2 = *(const float2*)((const float*)aux + idx);
                    *(float2*)((float*)O + idx) = make_float2(v0 + a2.x, v1 + a2.y);
                } else {
                    if (doSilu) {
                        v0 = v0 / (1.f + __expf(-v0));
                        v1 = v1 / (1.f + __expf(-v1));
                    }
                    *(__half2*)((__half*)O + idx) = __floats2half2_rn(v0, v1);
                }
            }
        }
    }
}

// ---------------- gated GEMM: O = (GA .* GB) @ Bt^T + aux (fp32 out) -------
// A operand computed on the fly: sync double-buffered reg staging; B via cp.async.
__global__ void __launch_bounds__(256, 2) gemm_gate_kernel(
    const __half* __restrict__ GA, const __half* __restrict__ GB,
    const __half* __restrict__ Bt, const float* __restrict__ aux,
    float* __restrict__ O, int N, int K) {
    extern __shared__ __half sm[];
    __half* Asm = sm;                      // [2][128][AST]
    __half* Bsm = sm + 2 * 128 * AST;      // [STG][128][BST]
    uint32_t aBase = (uint32_t)__cvta_generic_to_shared(Asm);
    uint32_t bBase = (uint32_t)__cvta_generic_to_shared(Bsm);

    const int tid  = threadIdx.x;
    const int lane = tid & 31;
    const int warp = tid >> 5;
    const int wm   = warp & 1;
    const int wn   = warp >> 1;
    const int rowBase = blockIdx.y * 128;
    const int colBase = blockIdx.x * 128;
    const int lq = lane >> 2;
    const int lr = lane & 3;

    float acc[4][4][4];
#pragma unroll
    for (int i = 0; i < 4; i++)
#pragma unroll
        for (int j = 0; j < 4; j++)
#pragma unroll
            for (int t = 0; t < 4; t++) acc[i][j][t] = 0.f;

    const int T = K / KT;
    uint4 ra[2];

    auto loadA = [&](int kt) {
#pragma unroll
        for (int c0 = 0; c0 < 2; c0++) {
            int c = tid + c0 * 256;
            int r = c >> 2, k8 = (c & 3) * 8;
            size_t off = (size_t)(rowBase + r) * K + kt * KT + k8;
            uint4 a4 = *(const uint4*)(GA + off);
            uint4 b4 = *(const uint4*)(GB + off);
            __half2* ah = (__half2*)&a4;
            const __half2* bh = (const __half2*)&b4;
            ah[0] = __hmul2(ah[0], bh[0]);
            ah[1] = __hmul2(ah[1], bh[1]);
            ah[2] = __hmul2(ah[2], bh[2]);
            ah[3] = __hmul2(ah[3], bh[3]);
            ra[c0] = a4;
        }
    };
    auto stsA = [&](int buf) {
#pragma unroll
        for (int c0 = 0; c0 < 2; c0++) {
            int c = tid + c0 * 256;
            int r = c >> 2, k8 = (c & 3) * 8;
            *(uint4*)(Asm + buf * 128 * AST + r * AST + k8) = ra[c0];
        }
    };
    auto stageB = [&](int s, int kt) {
#pragma unroll
        for (int c0 = 0; c0 < 2; c0++) {
            int c = tid + c0 * 256;
            int r = c >> 2, k8 = (c & 3) * 8;
            cpa16(bBase + (uint32_t)(s * 128 * BST + r * BST + k8) * 2,
                  Bt + (size_t)(colBase + r) * K + kt * KT + k8);
        }
    };

    loadA(0); stsA(0);
    stageB(0, 0); cpcommit();
    stageB(1, 1); cpcommit();
    if (T > 1) loadA(1);

    const int aRowSel = lane & 15;
    const int aKSel   = (lane >> 4) << 3;
    const int bRowSel = (lane & 7) + ((lane >> 4) << 3);
    const int bKSel   = ((lane >> 3) & 1) << 3;

    for (int t = 0; t < T; t++) {
        cpwait1();
        __syncthreads();
        if (t + 2 < T) stageB((t + 2) % STG, t + 2);
        cpcommit();

        const uint32_t aTile = aBase + (uint32_t)((t & 1) * 128 * AST) * 2;
        const uint32_t bTile = bBase + (uint32_t)((t % STG) * 128 * BST) * 2;
#pragma unroll
        for (int kf = 0; kf < 2; kf++) {
            const int k0 = kf * 16;
            uint32_t af[4][4];
#pragma unroll
            for (int mf = 0; mf < 4; mf++) {
                int r0 = wm * 64 + mf * 16;
                ldsm_x4(af[mf][0], af[mf][1], af[mf][2], af[mf][3],
                        aTile + (uint32_t)((r0 + aRowSel) * AST + k0 + aKSel) * 2);
            }
#pragma unroll
            for (int ng = 0; ng < 2; ng++) {
                int c0 = wn * 32 + ng * 16;
                uint32_t b0, b1, b2, b3;
                ldsm_x4(b0, b1, b2, b3,
                        bTile + (uint32_t)((c0 + bRowSel) * BST + k0 + bKSel) * 2);
#pragma unroll
                for (int mf = 0; mf < 4; mf++) {
                    mma_f16(acc[mf][2 * ng],     af[mf][0], af[mf][1], af[mf][2], af[mf][3], b0, b1);
                    mma_f16(acc[mf][2 * ng + 1], af[mf][0], af[mf][1], af[mf][2], af[mf][3], b2, b3);
                }
            }
        }
        if (t + 1 < T) {
            stsA((t + 1) & 1);
            if (t + 2 < T) loadA(t + 2);
        }
    }
    __syncthreads();

#pragma unroll
    for (int mf = 0; mf < 4; mf++) {
        int row0 = rowBase + wm * 64 + mf * 16 + lq;
#pragma unroll
        for (int nf = 0; nf < 4; nf++) {
            int col = colBase + wn * 32 + nf * 8 + 2 * lr;
#pragma unroll
            for (int hh = 0; hh < 2; hh++) {
                int row = row0 + hh * 8;
                size_t idx = (size_t)row * N + col;
                float2 a2 = *(const float2*)(aux + idx);
                *(float2*)(O + idx) = make_float2(acc[mf][nf][hh * 2] + a2.x,
                                                  acc[mf][nf][hh * 2 + 1] + a2.y);
            }
        }
    }
}

// ---------------- Flash attention, FP16 mma (causal, GQA), cp.async K/V ----
#define VST 72
#define FLASH_SMEM (6 * 64 * VST * 2)

__global__ void __launch_bounds__(128) flash_f16_kernel(
    const __half* __restrict__ q, const __half* __restrict__ k,
    const __half* __restrict__ v, __half* __restrict__ o) {
    extern __shared__ __half smh[];
    __half* Qh = smh;
    __half* Kh = smh + 64 * VST;
    __half* Vh = smh + 3 * 64 * VST;
    __half* Ph = smh + 5 * 64 * VST;
    uint32_t qhBase = (uint32_t)__cvta_generic_to_shared(Qh);
    uint32_t kBase  = (uint32_t)__cvta_generic_to_shared(Kh);
    uint32_t vBase  = (uint32_t)__cvta_generic_to_shared(Vh);
    uint32_t phBase = (uint32_t)__cvta_generic_to_shared(Ph);

    const int qb  = (gridDim.x - 1) - blockIdx.x;
    const int bh  = blockIdx.y;
    const int b   = bh / NH;
    const int h   = bh % NH;
    const int kvh = h / (NH / NKV);
    const int tid  = threadIdx.x;
    const int lane = tid & 31;
    const int warp = tid >> 5;
    const int lq = lane >> 2;
    const int lr = lane & 3;

    for (int t = tid; t < 64 * 8; t += 128) {
        int r = t >> 3, c8 = (t & 7) * 8;
        uint4 raw = *(const uint4*)(q + ((size_t)((b * S_LEN + qb * 64 + r) * NH + h)) * HDIM + c8);
        *(uint4*)(Qh + r * VST + c8) = raw;
    }

    auto stageKV = [&](int buf, int kb) {
        for (int t = tid; t < 64 * 8; t += 128) {
            int r = t >> 3, c8 = (t & 7) * 8;
            size_t goff = ((size_t)((b * S_LEN + kb * 64 + r) * NKV + kvh)) * HDIM + c8;
            uint32_t soff = (uint32_t)(buf * 64 * VST + r * VST + c8) * 2;
            cpa16(kBase + soff, k + goff);
            cpa16(vBase + soff, v + goff);
        }
    };
    stageKV(0, 0); cpcommit();

    const int wrow = warp * 16;
    const int r0l = wrow + lq;
    const int qrow0 = qb * 64 + r0l;
    const int qrow1 = qrow0 + 8;

    const int aRowSel = lane & 15;
    const int aKSel   = (lane >> 4) << 3;
    const int bRowSel = (lane & 7) + ((lane >> 4) << 3);
    const int bKSel   = ((lane >> 3) & 1) << 3;

    float m0 = -1e30f, m1 = -1e30f, l0 = 0.f, l1 = 0.f;
    float oacc[8][4];
#pragma unroll
    for (int nf = 0; nf < 8; nf++)
#pragma unroll
        for (int t = 0; t < 4; t++) oacc[nf][t] = 0.f;

    for (int kb = 0; kb <= qb; kb++) {
        const int buf = kb & 1;
        cpwait0();
        __syncthreads();
        if (kb + 1 <= qb) { stageKV(buf ^ 1, kb + 1); cpcommit(); }

        const uint32_t kTile = kBase + (uint32_t)(buf * 64 * VST) * 2;

        float sacc[8][4];
#pragma unroll
        for (int nf = 0; nf < 8; nf++)
#pragma unroll
            for (int t = 0; t < 4; t++) sacc[nf][t] = 0.f;

#pragma unroll
        for (int kf = 0; kf < 4; kf++) {
            const int k0 = kf * 16;
            uint32_t a0, a1, a2, a3;
            ldsm_x4(a0, a1, a2, a3,
                    qhBase + (uint32_t)((wrow + aRowSel) * VST + k0 + aKSel) * 2);
#pragma unroll
            for (int ng = 0; ng < 4; ng++) {
                int c0 = ng * 16;
                uint32_t b0, b1, b2, b3;
                ldsm_x4(b0, b1, b2, b3,
                        kTile + (uint32_t)((c0 + bRowSel) * VST + k0 + bKSel) * 2);
                mma_f16(sacc[2 * ng],     a0, a1, a2, a3, b0, b1);
                mma_f16(sacc[2 * ng + 1], a0, a1, a2, a3, b2, b3);
            }
        }

        const bool diag = (kb == qb);
        float rmax0 = -1e30f, rmax1 = -1e30f;
#pragma unroll
        for (int nf = 0; nf < 8; nf++) {
            int jc = kb * 64 + nf * 8 + 2 * lr;
            float s0 = sacc[nf][0] * 0.125f;
            float s1 = sacc[nf][1] * 0.125f;
            float s2 = sacc[nf][2] * 0.125f;
            float s3 = sacc[nf][3] * 0.125f;
            if (diag) {
                if (jc     > qrow0) s0 = -1e30f;
                if (jc + 1 > qrow0) s1 = -1e30f;
                if (jc     > qrow1) s2 = -1e30f;
                if (jc + 1 > qrow1) s3 = -1e30f;
            }
            sacc[nf][0] = s0; sacc[nf][1] = s1; sacc[nf][2] = s2; sacc[nf][3] = s3;
            rmax0 = fmaxf(rmax0, fmaxf(s0, s1));
            rmax1 = fmaxf(rmax1, fmaxf(s2, s3));
        }
        rmax0 = fmaxf(rmax0, __shfl_xor_sync(0xffffffffu, rmax0, 1));
        rmax0 = fmaxf(rmax0, __shfl_xor_sync(0xffffffffu, rmax0, 2));
        rmax1 = fmaxf(rmax1, __shfl_xor_sync(0xffffffffu, rmax1, 1));
        rmax1 = fmaxf(rmax1, __shfl_xor_sync(0xffffffffu, rmax1, 2));

        float mn0 = fmaxf(m0, rmax0);
        float mn1 = fmaxf(m1, rmax1);
        float alpha0 = __expf(m0 - mn0);
        float alpha1 = __expf(m1 - mn1);
        m0 = mn0; m1 = mn1;

        float rsum0 = 0.f, rsum1 = 0.f;
#pragma unroll
        for (int nf = 0; nf < 8; nf++) {
            float p0 = __expf(sacc[nf][0] - mn0);
            float p1 = __expf(sacc[nf][1] - mn0);
            float p2 = __expf(sacc[nf][2] - mn1);
            float p3 = __expf(sacc[nf][3] - mn1);
            sacc[nf][0] = p0; sacc[nf][1] = p1; sacc[nf][2] = p2; sacc[nf][3] = p3;
            rsum0 += p0 + p1;
            rsum1 += p2 + p3;
        }
        rsum0 += __shfl_xor_sync(0xffffffffu, rsum0, 1);
        rsum0 += __shfl_xor_sync(0xffffffffu, rsum0, 2);
        rsum1 += __shfl_xor_sync(0xffffffffu, rsum1, 1);
        rsum1 += __shfl_xor_sync(0xffffffffu, rsum1, 2);
        l0 = l0 * alpha0 + rsum0;
        l1 = l1 * alpha1 + rsum1;

#pragma unroll
        for (int nf = 0; nf < 8; nf++) {
            oacc[nf][0] *= alpha0; oacc[nf][1] *= alpha0;
            oacc[nf][2] *= alpha1; oacc[nf][3] *= alpha1;
        }

#pragma unroll
        for (int nf = 0; nf < 8; nf++) {
            int pc = nf * 8 + 2 * lr;
            *(__half2*)(Ph + r0l * VST + pc)       = __floats2half2_rn(sacc[nf][0], sacc[nf][1]);
            *(__half2*)(Ph + (r0l + 8) * VST + pc) = __floats2half2_rn(sacc[nf][2], sacc[nf][3]);
        }
        __syncwarp();

        const uint32_t vTile = vBase + (uint32_t)(buf * 64 * VST) * 2;
#pragma unroll
        for (int kf = 0; kf < 4; kf++) {
            const int k0 = kf * 16;
            uint32_t a0, a1, a2, a3;
            ldsm_x4(a0, a1, a2, a3,
                    phBase + (uint32_t)((wrow + aRowSel) * VST + k0 + aKSel) * 2);
#pragma unroll
            for (int np = 0; np < 4; np++) {
                const int d0 = np * 16;
                uint32_t addr = vTile +
                    (uint32_t)((k0 + (lane & 15)) * VST + d0 + ((lane & 16) >> 1)) * 2;
                uint32_t bb0, bb1, bb2, bb3;
                asm volatile(
                    "ldmatrix.sync.aligned.m8n8.x4.trans.shared.b16 {%0,%1,%2,%3}, [%4];"
                    : "=r"(bb0), "=r"(bb1), "=r"(bb2), "=r"(bb3) : "r"(addr));
                mma_f16(oacc[2 * np],     a0, a1, a2, a3, bb0, bb1);
                mma_f16(oacc[2 * np + 1], a0, a1, a2, a3, bb2, bb3);
            }
        }
    }

    float inv0 = 1.f / l0;
    float inv1 = 1.f / l1;
    int grow0 = b * S_LEN + qrow0;
    int grow1 = b * S_LEN + qrow1;
#pragma unroll
    for (int nf = 0; nf < 8; nf++) {
        int col = nf * 8 + 2 * lr;
        *(__half2*)(o + ((size_t)(grow0 * NH + h)) * HDIM + col) =
            __floats2half2_rn(oacc[nf][0] * inv0, oacc[nf][1] * inv0);
        *(__half2*)(o + ((size_t)(grow1 * NH + h)) * HDIM + col) =
            __floats2half2_rn(oacc[nf][2] * inv1, oacc[nf][3] * inv1);
    }
}

// ---------------- launch ----------------
extern "C" void kernel_launch(void* const* d_in, const int* in_sizes, int n_in,
                              void* d_out, int out_size) {
    const float* x  = (const float*)d_in[0];
    const float* Wq = (const float*)d_in[1];
    const float* Wk = (const float*)d_in[2];
    const float* Wv = (const float*)d_in[3];
    const float* Wo = (const float*)d_in[4];
    const float* an = (const float*)d_in[5];
    const float* w0 = (const float*)d_in[6];
    const float* w1 = (const float*)d_in[7];
    const float* w2 = (const float*)d_in[8];
    const float* sn = (const float*)d_in[9];
    const float* on = (const float*)d_in[10];
    float* out = (float*)d_out;

    __half *h, *q, *k, *v, *att, *gate, *gate2;
    __half *hWq, *hWk, *hWv, *hWo, *hw0, *hw1, *hw2;
    float *x1, *x2, *cosT, *sinT;
    cudaGetSymbolAddress((void**)&h,     g_h);
    cudaGetSymbolAddress((void**)&q,     g_q);
    cudaGetSymbolAddress((void**)&k,     g_k);
    cudaGetSymbolAddress((void**)&v,     g_v);
    cudaGetSymbolAddress((void**)&att,   g_att);
    cudaGetSymbolAddress((void**)&gate,  g_gate);
    cudaGetSymbolAddress((void**)&gate2, g_gate2);
    cudaGetSymbolAddress((void**)&x1,    g_x1);
    cudaGetSymbolAddress((void**)&x2,    g_x2);
    cudaGetSymbolAddress((void**)&cosT,  g_cosT);
    cudaGetSymbolAddress((void**)&sinT,  g_sinT);
    cudaGetSymbolAddress((void**)&hWq,   g_hWq);
    cudaGetSymbolAddress((void**)&hWk,   g_hWk);
    cudaGetSymbolAddress((void**)&hWv,   g_hWv);
    cudaGetSymbolAddress((void**)&hWo,   g_hWo);
    cudaGetSymbolAddress((void**)&hw0,   g_hw0);
    cudaGetSymbolAddress((void**)&hw1,   g_hw1);
    cudaGetSymbolAddress((void**)&hw2,   g_hw2);

    cudaFuncSetAttribute(flash_f16_kernel,
                         cudaFuncAttributeMaxDynamicSharedMemorySize, FLASH_SMEM);
    cudaFuncSetAttribute(gemm_f16_kernel,
                         cudaFuncAttributeMaxDynamicSharedMemorySize, GEMM_SMEM);
    cudaFuncSetAttribute(qkv_gemm_kernel,
                         cudaFuncAttributeMaxDynamicSharedMemorySize, GEMM_SMEM);
    cudaFuncSetAttribute(gemm_gate_kernel,
                         cudaFuncAttributeMaxDynamicSharedMemorySize, GATE_SMEM);

    // one-time stream/event setup (host-side objects, created on first
    // non-capture call; reused on capture — no work-determinism impact)
    static cudaStream_t s2 = nullptr;
    static cudaEvent_t ev0, ev1, ev2;
    if (!s2) {
        cudaStreamCreateWithFlags(&s2, cudaStreamNonBlocking);
        cudaEventCreateWithFlags(&ev0, cudaEventDisableTiming);
        cudaEventCreateWithFlags(&ev1, cudaEventDisableTiming);
        cudaEventCreateWithFlags(&ev2, cudaEventDisableTiming);
    }

    const dim3 tb(32, 8);
    const dim3 gQKV (10, M_TOK / 128, 1);
    const dim3 gN768(DMODEL / 128, M_TOK / 128, 1);
    const dim3 gFF2 (FFDIM / 128,  M_TOK / 128, 2);

    // fork side stream
    cudaEventRecord(ev0, 0);
    cudaStreamWaitEvent(s2, ev0, 0);

    // k0 (default)
    rope_table_kernel<<<(S_LEN * 32 + 255) / 256, 256>>>(cosT, sinT);
    // k1..k3 (s2): QKV weight transposes
    w_t_h_kernel<<<dim3(DMODEL / 32, DMODEL / 32, NLAYER), tb, 0, s2>>>(Wq, hWq, DMODEL, DMODEL);
    w_t_h_kernel<<<dim3(KVD / 32,    DMODEL / 32, NLAYER), tb, 0, s2>>>(Wk, hWk, DMODEL, KVD);
    w_t_h_kernel<<<dim3(KVD / 32,    DMODEL / 32, NLAYER), tb, 0, s2>>>(Wv, hWv, DMODEL, KVD);
    cudaEventRecord(ev1, s2);
    // k4 (default)
    rmsnorm_kernel<<<M_TOK, 256>>>(x, an, h, nullptr);
    cudaStreamWaitEvent(0, ev1, 0);
    // k5 (default)  <- ncu -s 5 -c 1 captures this
    qkv_gemm_kernel<<<gQKV, 256, GEMM_SMEM>>>(h, hWq, hWk, hWv, q, k, v, cosT, sinT);
    // remaining transposes on s2, overlapped with QKV + flash
    w_t_h_kernel<<<dim3(DMODEL / 32, DMODEL / 32, NLAYER), tb, 0, s2>>>(Wo, hWo, DMODEL, DMODEL);
    w_t_h_kernel<<<dim3(FFDIM / 32,  DMODEL / 32, NLAYER), tb, 0, s2>>>(w0, hw0, DMODEL, FFDIM);
    w_t_h_kernel<<<dim3(FFDIM / 32,  DMODEL / 32, NLAYER), tb, 0, s2>>>(w1, hw1, DMODEL, FFDIM);
    w_t_h_kernel<<<dim3(DMODEL / 32, FFDIM / 32,  NLAYER), tb, 0, s2>>>(w2, hw2, FFDIM, DMODEL);
    cudaEventRecord(ev2, s2);

    flash_f16_kernel<<<dim3(S_LEN / 64, BATCH * NH), 128, FLASH_SMEM>>>(q, k, v, att);
    cudaStreamWaitEvent(0, ev2, 0);   // join side stream before Wo GEMM

    const float* xin = x;
    for (int l = 0; l < NLAYER; l++) {
        __half* hWq_l = hWq + (size_t)l * DMODEL * DMODEL;
        __half* hWk_l = hWk + (size_t)l * KVD * DMODEL;
        __half* hWv_l = hWv + (size_t)l * KVD * DMODEL;
        __half* hWo_l = hWo + (size_t)l * DMODEL * DMODEL;
        __half* hw0_l = hw0 + (size_t)l * FFDIM * DMODEL;
        __half* hw1_l = hw1 + (size_t)l * FFDIM * DMODEL;
        __half* hw2_l = hw2 + (size_t)l * DMODEL * FFDIM;

        if (l > 0) {
            rmsnorm_kernel<<<M_TOK, 256>>>(xin, an + l * DMODEL, h, nullptr);
            qkv_gemm_kernel<<<gQKV, 256, GEMM_SMEM>>>(h, hWq_l, hWk_l, hWv_l,
                                                      q, k, v, cosT, sinT);
            flash_f16_kernel<<<dim3(S_LEN / 64, BATCH * NH), 128, FLASH_SMEM>>>(q, k, v, att);
        }
        gemm_f16_kernel<<<gN768, 256, GEMM_SMEM>>>(att, hWo_l, hWo_l, xin, x1, x1, DMODEL, DMODEL, 3);
        rmsnorm_kernel<<<M_TOK, 256>>>(x1, sn + l * DMODEL, h, nullptr);
        // fused, parallel w0 & w1 (z=0: silu -> gate, z=1: plain -> gate2)
        gemm_f16_kernel<<<gFF2, 256, GEMM_SMEM>>>(h, hw0_l, hw1_l, nullptr, gate, gate2, FFDIM, DMODEL, 5);
        // x2 = (gate .* gate2) @ w2 + x1
        gemm_gate_kernel<<<gN768, 256, GATE_SMEM>>>(gate, gate2, hw2_l, x1, x2, DMODEL, FFDIM);
        xin = x2;
    }
    rmsnorm_kernel<<<M_TOK, 256>>>(x2, on, nullptr, out);
}